// round 2
// baseline (speedup 1.0000x reference)
#include <cuda_runtime.h>
#include <math.h>

// ---------------- scratch (device globals; no allocation) ----------------
__device__ float g_lat[5570560];      // 4 levels of (256,H,W) concatenated
__device__ float g_feas[27852800];    // 4 levels of (5,256,H,W) concatenated
__device__ float g_fsum[4 * 256];
__device__ float g_fz[4 * 128];
__device__ float g_att[4 * 5 * 256];

#define BN_EPS 1e-5f

// ---------------- lateral 1x1 conv as tiled SGEMM ----------------
// C[256,N] = A[256,K] * B[K,N] + bias ; writes to g_lat + latoff
__global__ __launch_bounds__(256)
void lateral_gemm(const float* __restrict__ A, const float* __restrict__ X,
                  const float* __restrict__ bias, int latoff, int K, int N)
{
    __shared__ float As[16][64];
    __shared__ float Bs[16][64];
    const int tx = threadIdx.x & 15;
    const int ty = threadIdx.x >> 4;
    const int row0 = blockIdx.y * 64;
    const int col0 = blockIdx.x * 64;

    float acc[4][4];
#pragma unroll
    for (int i = 0; i < 4; i++)
#pragma unroll
        for (int j = 0; j < 4; j++) acc[i][j] = 0.f;

    for (int k0 = 0; k0 < K; k0 += 16) {
#pragma unroll
        for (int i = 0; i < 4; i++) {
            int idx = threadIdx.x + i * 256;
            int r = idx >> 4, k = idx & 15;
            As[k][r] = A[(row0 + r) * K + k0 + k];
        }
#pragma unroll
        for (int i = 0; i < 4; i++) {
            int idx = threadIdx.x + i * 256;
            int k = idx >> 6, c = idx & 63;
            Bs[k][c] = X[(k0 + k) * N + col0 + c];
        }
        __syncthreads();
#pragma unroll
        for (int k = 0; k < 16; k++) {
            float4 a4 = *(const float4*)&As[k][ty * 4];
            float4 b4 = *(const float4*)&Bs[k][tx * 4];
            float a[4] = {a4.x, a4.y, a4.z, a4.w};
            float b[4] = {b4.x, b4.y, b4.z, b4.w};
#pragma unroll
            for (int i = 0; i < 4; i++)
#pragma unroll
                for (int j = 0; j < 4; j++) acc[i][j] = fmaf(a[i], b[j], acc[i][j]);
        }
        __syncthreads();
    }
    float* out = g_lat + latoff;
#pragma unroll
    for (int i = 0; i < 4; i++) {
        float bv = bias[row0 + ty * 4 + i];
#pragma unroll
        for (int j = 0; j < 4; j++)
            out[(row0 + ty * 4 + i) * N + col0 + tx * 4 + j] = acc[i][j] + bv;
    }
}

// ---------------- nearest 2x upsample-add (dst += up2(src)) ----------------
__global__ void up_add(int dstoff, int srcoff, int H, int W)
{
    int i4 = blockIdx.x * blockDim.x + threadIdx.x;
    int HW = H * W;
    int n4 = (256 * HW) >> 2;
    if (i4 >= n4) return;
    int hw4 = HW >> 2;
    int c = i4 / hw4;
    int rem = i4 - c * hw4;
    int w4 = W >> 2;
    int y = rem / w4;
    int x4 = rem - y * w4;
    int H2 = H >> 1, W2 = W >> 1;
    int selem = c * H2 * W2 + (y >> 1) * W2 + (x4 << 1);
    float2 sv = *(const float2*)(g_lat + srcoff + selem);
    float4* d = (float4*)(g_lat + dstoff) + i4;
    float4 dv = *d;
    dv.x += sv.x; dv.y += sv.x; dv.z += sv.y; dv.w += sv.y;
    *d = dv;
}

// ---------------- AAC conv: 5 rotated 3x3 convs fused, + bias + BN + relu --
// Tile: 32 out-channels x 8x8 pixels, 256 threads (thread = 1 oc x 1 row of 8 px)
__global__ __launch_bounds__(256)
void conv_aac(const float* __restrict__ w,     // [256][256][9] level slice
              const float* __restrict__ bias,  // [256]
              const float* __restrict__ bng, const float* __restrict__ bnb,
              const float* __restrict__ bnm, const float* __restrict__ bnv,
              int latoff, int feoff, int H, int W)
{
    // inverse rotation maps: weight j sits at tap INVK[r][j] in branch r
    constexpr int INVK[5][9] = {
        {0, 1, 2, 3, 4, 5, 6, 7, 8},
        {1, 2, 5, 0, 4, 8, 3, 6, 7},
        {2, 5, 8, 1, 4, 7, 0, 3, 6},
        {5, 8, 7, 2, 4, 6, 1, 0, 3},
        {8, 7, 6, 5, 4, 3, 2, 1, 0}};

    __shared__ float s_w[8][32][9];    // [ic][oc][j]
    __shared__ float s_in[8][10][10];  // haloed input patch

    const int tid = threadIdx.x;
    const int ocl = tid >> 3;   // 0..31
    const int ty  = tid & 7;    // 0..7 (output row within tile)
    const int x0  = blockIdx.x * 8;
    const int y0  = blockIdx.y * 8;
    const int ocb = blockIdx.z * 32;
    const float* lat = g_lat + latoff;

    float acc[5][8];
#pragma unroll
    for (int r = 0; r < 5; r++)
#pragma unroll
        for (int p = 0; p < 8; p++) acc[r][p] = 0.f;

    for (int ic0 = 0; ic0 < 256; ic0 += 8) {
        __syncthreads();
        // weights: 32 oc x 8 ic x 9 taps = 2304 floats, coalesced 72-float runs
#pragma unroll
        for (int i = 0; i < 9; i++) {
            int t = tid + i * 256;
            int oc = t / 72;
            int rem = t - oc * 72;  // rem = icl*9 + j
            s_w[rem / 9][oc][rem % 9] = w[(ocb + oc) * 2304 + ic0 * 9 + rem];
        }
        // input: 8 ic x 10x10 haloed patch, zero-padded at borders
        for (int t = tid; t < 800; t += 256) {
            int ic = t / 100;
            int rem = t - ic * 100;
            int yy = rem / 10, xx = rem - (rem / 10) * 10;
            int gy = y0 + yy - 1, gx = x0 + xx - 1;
            float v = 0.f;
            if (gy >= 0 && gy < H && gx >= 0 && gx < W)
                v = lat[(ic0 + ic) * H * W + gy * W + gx];
            s_in[ic][yy][xx] = v;
        }
        __syncthreads();

        for (int ic = 0; ic < 8; ic++) {
            float row[3][10];
#pragma unroll
            for (int d = 0; d < 3; d++)
#pragma unroll
                for (int t = 0; t < 10; t++) row[d][t] = s_in[ic][ty + d][t];
            float w9[9];
#pragma unroll
            for (int j = 0; j < 9; j++) w9[j] = s_w[ic][ocl][j];
#pragma unroll
            for (int j = 0; j < 9; j++) {
#pragma unroll
                for (int r = 0; r < 5; r++) {
                    const int k  = INVK[r][j];
                    const int ky = k / 3, kx = k % 3;
#pragma unroll
                    for (int p = 0; p < 8; p++)
                        acc[r][p] = fmaf(w9[j], row[ky][p + kx], acc[r][p]);
                }
            }
        }
    }

    // epilogue: + conv bias, BN, relu -> feas
    const int oc = ocb + ocl;
    const float bv = bias[oc];
    float* fo = g_feas + feoff;
    const int yy = y0 + ty;
#pragma unroll
    for (int r = 0; r < 5; r++) {
        float g = bng[r * 256 + oc];
        float b = bnb[r * 256 + oc];
        float m = bnm[r * 256 + oc];
        float v = bnv[r * 256 + oc];
        float sc = g * rsqrtf(v + BN_EPS);
        float vals[8];
#pragma unroll
        for (int p = 0; p < 8; p++) {
            float t = (acc[r][p] + bv - m) * sc + b;
            vals[p] = fmaxf(t, 0.f);
        }
        float4* dst = (float4*)&fo[(((size_t)r * 256 + oc) * H + yy) * W + x0];
        dst[0] = make_float4(vals[0], vals[1], vals[2], vals[3]);
        dst[1] = make_float4(vals[4], vals[5], vals[6], vals[7]);
    }
}

// ---------------- fea_s = mean over (branch-sum, H, W) ----------------
__global__ void reduce_fsum(int feoff, int HW, float inv, int outoff)
{
    int c = blockIdx.x;
    const float* f = g_feas + feoff;
    float s = 0.f;
    for (int r = 0; r < 5; r++) {
        const float* p = f + ((size_t)(r * 256 + c)) * HW;
        for (int i = threadIdx.x; i < HW; i += blockDim.x) s += p[i];
    }
    __shared__ float sm[256];
    sm[threadIdx.x] = s;
    __syncthreads();
    for (int o = 128; o > 0; o >>= 1) {
        if (threadIdx.x < o) sm[threadIdx.x] += sm[threadIdx.x + o];
        __syncthreads();
    }
    if (threadIdx.x == 0) g_fsum[outoff + c] = sm[0] * inv;
}

// ---------------- fea_z = fc_w @ fea_s + fc_b ----------------
__global__ void fz_kernel(const float* __restrict__ fcw, const float* __restrict__ fcb,
                          int fsoff, int fzoff)
{
    int g = threadIdx.x >> 4;
    int lane = threadIdx.x & 15;
    int d = blockIdx.x * 16 + g;
    float s = 0.f;
    for (int c = lane; c < 256; c += 16) s += fcw[d * 256 + c] * g_fsum[fsoff + c];
#pragma unroll
    for (int o = 8; o > 0; o >>= 1) s += __shfl_down_sync(0xffffffffu, s, o, 16);
    if (lane == 0) g_fz[fzoff + d] = s + fcb[d];
}

// ---------------- att = softmax_m(fcs_w @ fea_z + fcs_b) ----------------
__global__ void att_kernel(const float* __restrict__ fcsw, const float* __restrict__ fcsb,
                           int fzoff, int attoff)
{
    __shared__ float fz[128];
    if (threadIdx.x < 128) fz[threadIdx.x] = g_fz[fzoff + threadIdx.x];
    __syncthreads();
    int cl = threadIdx.x >> 5;
    int lane = threadIdx.x & 31;
    int c = blockIdx.x * 8 + cl;
    float lg[5];
#pragma unroll
    for (int m = 0; m < 5; m++) {
        float s = 0.f;
#pragma unroll
        for (int i = 0; i < 4; i++) {
            int d = lane + i * 32;
            s += fz[d] * fcsw[((m * 256 + c) * 128) + d];
        }
#pragma unroll
        for (int o = 16; o > 0; o >>= 1) s += __shfl_down_sync(0xffffffffu, s, o);
        lg[m] = s;
    }
    if (lane == 0) {
        float mx = -1e30f;
#pragma unroll
        for (int m = 0; m < 5; m++) {
            lg[m] += fcsb[m * 256 + c];
            mx = fmaxf(mx, lg[m]);
        }
        float den = 0.f;
#pragma unroll
        for (int m = 0; m < 5; m++) { lg[m] = expf(lg[m] - mx); den += lg[m]; }
        float inv = 1.f / den;
#pragma unroll
        for (int m = 0; m < 5; m++) g_att[attoff + m * 256 + c] = lg[m] * inv;
    }
}

// ---------------- out = sum_m feas[m] * att[m] ----------------
__global__ void wsum_kernel(int feoff, int attoff, float* __restrict__ out, int HW)
{
    int i4 = blockIdx.x * blockDim.x + threadIdx.x;
    int n4 = (256 * HW) >> 2;
    if (i4 >= n4) return;
    int hw4 = HW >> 2;
    int c = i4 / hw4;
    int p = i4 - c * hw4;
    const float4* f = (const float4*)(g_feas + feoff);
    float4 acc = make_float4(0.f, 0.f, 0.f, 0.f);
#pragma unroll
    for (int m = 0; m < 5; m++) {
        float a = g_att[attoff + m * 256 + c];
        float4 v = f[((size_t)(m * 256 + c)) * hw4 + p];
        acc.x = fmaf(a, v.x, acc.x);
        acc.y = fmaf(a, v.y, acc.y);
        acc.z = fmaf(a, v.z, acc.z);
        acc.w = fmaf(a, v.w, acc.w);
    }
    ((float4*)out)[i4] = acc;
}

// ---------------- launch ----------------
extern "C" void kernel_launch(void* const* d_in, const int* in_sizes, int n_in,
                              void* d_out, int out_size)
{
    // Input ordering: setup_inputs() builds the dict interleaved
    // (x0, lw0, x1, lw1, ...). Detect which ordering metadata used via
    // in_sizes[1]: lw0 = 256*256 = 65536 (interleaved) vs x1 = 512*64*64
    // = 2097152 (grouped).
    const float *x[4], *lw[4];
    if (in_sizes[1] == 65536) {           // interleaved: x0,lw0,x1,lw1,...
        for (int i = 0; i < 4; i++) {
            x[i]  = (const float*)d_in[2 * i];
            lw[i] = (const float*)d_in[2 * i + 1];
        }
    } else {                              // grouped: x0..x3, lw0..lw3
        for (int i = 0; i < 4; i++) {
            x[i]  = (const float*)d_in[i];
            lw[i] = (const float*)d_in[4 + i];
        }
    }
    const float* lb   = (const float*)d_in[8];
    const float* aacw = (const float*)d_in[9];
    const float* aacb = (const float*)d_in[10];
    const float* bng  = (const float*)d_in[11];
    const float* bnb  = (const float*)d_in[12];
    const float* bnm  = (const float*)d_in[13];
    const float* bnv  = (const float*)d_in[14];
    const float* fcw  = (const float*)d_in[15];
    const float* fcb  = (const float*)d_in[16];
    const float* fcsw = (const float*)d_in[17];
    const float* fcsb = (const float*)d_in[18];
    float* out = (float*)d_out;

    static const int Hs[4]      = {128, 64, 32, 16};
    static const int cins[4]    = {256, 512, 1024, 2048};
    static const int latOff[4]  = {0, 4194304, 5242880, 5505024};
    static const int feasOff[4] = {0, 20971520, 26214400, 27525120};

    // 1) lateral 1x1 convs
    for (int i = 0; i < 4; i++) {
        int N = Hs[i] * Hs[i];
        dim3 g(N / 64, 4);
        lateral_gemm<<<g, 256>>>(lw[i], x[i], lb + i * 256, latOff[i], cins[i], N);
    }
    // 2) top-down pathway
    for (int i = 3; i >= 1; i--) {
        int Hd = Hs[i - 1];
        int n4 = 256 * Hd * Hd / 4;
        up_add<<<(n4 + 255) / 256, 256>>>(latOff[i - 1], latOff[i], Hd, Hd);
    }
    // 3) per-level AAC conv + SK fusion
    for (int i = 0; i < 4; i++) {
        int H = Hs[i];
        int HW = H * H;
        dim3 g(H / 8, H / 8, 8);
        conv_aac<<<g, 256>>>(aacw + i * 589824, aacb + i * 256,
                             bng + i * 1280, bnb + i * 1280,
                             bnm + i * 1280, bnv + i * 1280,
                             latOff[i], feasOff[i], H, H);
        reduce_fsum<<<256, 256>>>(feasOff[i], HW, 1.f / (float)HW, i * 256);
        fz_kernel<<<8, 256>>>(fcw + i * 128 * 256, fcb + i * 128, i * 256, i * 128);
        att_kernel<<<32, 256>>>(fcsw + i * 5 * 256 * 128, fcsb + i * 5 * 256,
                                i * 128, i * 1280);
        int n4 = 256 * HW / 4;
        wsum_kernel<<<(n4 + 255) / 256, 256>>>(feasOff[i], i * 1280, out + latOff[i], HW);
    }
    (void)n_in; (void)out_size;
}

// round 4
// speedup vs baseline: 1.5608x; 1.5608x over previous
#include <cuda_runtime.h>
#include <cstdint>
#include <math.h>

// ---------------- scratch (device globals; no allocation) ----------------
__device__ float g_lat[5570560];      // 4 levels of (256,H,W)
__device__ float g_feas[27852800];    // 4 levels of (5,256,H,W)
__device__ float g_wt[2359296];       // tf32 weights, mma-fragment order
__device__ float g_part[2097152];     // split-K partials
__device__ float g_fsum[4 * 256];
__device__ float g_fz[4 * 128];
__device__ float g_att[4 * 5 * 256];

#define BN_EPS 1e-5f

__device__ __forceinline__ float tf32r(float x) {
    uint32_t u;
    asm("cvt.rn.tf32.f32 %0, %1;" : "=r"(u) : "f"(x));
    return __uint_as_float(u);
}

__device__ __forceinline__ void mma8(float* c, const uint32_t* a,
                                     uint32_t b0, uint32_t b1) {
    asm volatile(
        "mma.sync.aligned.m16n8k8.row.col.f32.tf32.tf32.f32 "
        "{%0,%1,%2,%3}, {%4,%5,%6,%7}, {%8,%9}, {%0,%1,%2,%3};"
        : "+f"(c[0]), "+f"(c[1]), "+f"(c[2]), "+f"(c[3])
        : "r"(a[0]), "r"(a[1]), "r"(a[2]), "r"(a[3]), "r"(b0), "r"(b1));
}

// ---------------- weight transpose + tf32 round (fragment order) ----------
// For j, kc(32 k8-chunks), t(16 m16-tiles), lane(32), q(4):
//   oc = t*16 + (lane>>2) + 8*(q&1);  ic = kc*8 + (lane&3) + 4*(q>>1)
// g_wt[(((lvl*9+j)*32+kc)*16+t)*128 + lane*4 + q] = tf32(aacw[lvl][oc][ic][j])
__global__ void wt_transpose(const float* __restrict__ aacw)
{
    int idx = blockIdx.x * 256 + threadIdx.x;
    if (idx >= 2359296) return;
    int q = idx & 3;
    int l = (idx >> 2) & 31;
    int t = (idx >> 7) & 15;
    int kc = (idx >> 11) & 31;
    int lj = idx >> 16;           // lvl*9 + j
    int j = lj % 9, lvl = lj / 9;
    int oc = t * 16 + (l >> 2) + 8 * (q & 1);
    int ic = kc * 8 + (l & 3) + 4 * (q >> 1);
    g_wt[idx] = tf32r(aacw[((lvl * 256 + oc) * 256 + ic) * 9 + j]);
}

// ---------------- round lat to tf32 (RN) in place ----------------
__global__ void round_lat()
{
    int i = blockIdx.x * 256 + threadIdx.x;
    if (i >= 1392640) return;
    float4* p = (float4*)g_lat + i;
    float4 v = *p;
    v.x = tf32r(v.x); v.y = tf32r(v.y); v.z = tf32r(v.z); v.w = tf32r(v.w);
    *p = v;
}

// ---------------- lateral 1x1 conv as tiled SGEMM (split-K capable) -------
__global__ __launch_bounds__(256)
void lateral_gemm(const float* __restrict__ A, const float* __restrict__ X,
                  const float* __restrict__ bias, float* __restrict__ outp,
                  int K, int kLen, int N, int addbias)
{
    __shared__ float As[16][64];
    __shared__ float Bs[16][64];
    const int tx = threadIdx.x & 15;
    const int ty = threadIdx.x >> 4;
    const int row0 = blockIdx.y * 64;
    const int col0 = blockIdx.x * 64;
    const int kb = blockIdx.z * kLen;

    float acc[4][4];
#pragma unroll
    for (int i = 0; i < 4; i++)
#pragma unroll
        for (int j = 0; j < 4; j++) acc[i][j] = 0.f;

    for (int k0 = kb; k0 < kb + kLen; k0 += 16) {
#pragma unroll
        for (int i = 0; i < 4; i++) {
            int idx = threadIdx.x + i * 256;
            int r = idx >> 4, k = idx & 15;
            As[k][r] = A[(row0 + r) * K + k0 + k];
        }
#pragma unroll
        for (int i = 0; i < 4; i++) {
            int idx = threadIdx.x + i * 256;
            int k = idx >> 6, c = idx & 63;
            Bs[k][c] = X[(k0 + k) * N + col0 + c];
        }
        __syncthreads();
#pragma unroll
        for (int k = 0; k < 16; k++) {
            float4 a4 = *(const float4*)&As[k][ty * 4];
            float4 b4 = *(const float4*)&Bs[k][tx * 4];
            float a[4] = {a4.x, a4.y, a4.z, a4.w};
            float b[4] = {b4.x, b4.y, b4.z, b4.w};
#pragma unroll
            for (int i = 0; i < 4; i++)
#pragma unroll
                for (int j = 0; j < 4; j++) acc[i][j] = fmaf(a[i], b[j], acc[i][j]);
        }
        __syncthreads();
    }
    float* out = outp + (size_t)blockIdx.z * 256 * N;
#pragma unroll
    for (int i = 0; i < 4; i++) {
        float bv = addbias ? bias[row0 + ty * 4 + i] : 0.f;
#pragma unroll
        for (int j = 0; j < 4; j++)
            out[(row0 + ty * 4 + i) * N + col0 + tx * 4 + j] = acc[i][j] + bv;
    }
}

// reduce split-K partials + bias -> g_lat
__global__ void reduce_part(int latoff, const float* __restrict__ lb, int N, int S)
{
    int idx = blockIdx.x * 256 + threadIdx.x;
    if (idx >= 256 * N) return;
    float s = lb[idx / N];
    for (int z = 0; z < S; z++) s += g_part[(size_t)z * 256 * N + idx];
    g_lat[latoff + idx] = s;
}

// ---------------- nearest 2x upsample-add (dst += up2(src)) ----------------
__global__ void up_add(int dstoff, int srcoff, int H, int W)
{
    int i4 = blockIdx.x * blockDim.x + threadIdx.x;
    int HW = H * W;
    int n4 = (256 * HW) >> 2;
    if (i4 >= n4) return;
    int hw4 = HW >> 2;
    int c = i4 / hw4;
    int rem = i4 - c * hw4;
    int w4 = W >> 2;
    int y = rem / w4;
    int x4 = rem - y * w4;
    int H2 = H >> 1, W2 = W >> 1;
    int selem = c * H2 * W2 + (y >> 1) * W2 + (x4 << 1);
    float2 sv = *(const float2*)(g_lat + srcoff + selem);
    float4* d = (float4*)(g_lat + dstoff) + i4;
    float4 dv = *d;
    dv.x += sv.x; dv.y += sv.x; dv.z += sv.y; dv.w += sv.y;
    *d = dv;
}

// ---------------- AAC conv via mma.sync tf32 implicit GEMM ----------------
// grid: (HW/128, 10). mb -> branch r = mb/2, oc0 = (mb&1)*128.
// CTA: M=128 x N=128 px, 8 warps (4m x 2n), warp tile 32x64.
// K = 2304 tap-major: j(9) x icb(8) chunks of 32 (4 k8 steps each).
__global__ __launch_bounds__(256)
void conv_aac_mma(const float* __restrict__ bias,
                  const float* __restrict__ bng, const float* __restrict__ bnb,
                  const float* __restrict__ bnm, const float* __restrict__ bnv,
                  int latoff, int feoff, int wtoff4, int H, int W, int lw)
{
    constexpr int ROT[5][9] = {
        {0, 1, 2, 3, 4, 5, 6, 7, 8},
        {3, 0, 1, 6, 4, 2, 7, 8, 5},
        {6, 3, 0, 7, 4, 1, 8, 5, 2},
        {7, 6, 3, 8, 4, 0, 5, 2, 1},
        {8, 7, 6, 5, 4, 3, 2, 1, 0}};

    __shared__ float Bs[32][128];

    const int tid = threadIdx.x;
    const int wid = tid >> 5, lid = tid & 31;
    const int g = lid >> 2, tig = lid & 3;
    const int warp_m = wid & 3, warp_n = wid >> 2;
    const int pb = blockIdx.x;
    const int mb = blockIdx.y;
    const int HW = H * W;
    const int r = mb >> 1;
    const int oc0 = (mb & 1) * 128;

    float c[2][8][4];
#pragma unroll
    for (int mt = 0; mt < 2; mt++)
#pragma unroll
        for (int nt = 0; nt < 8; nt++)
#pragma unroll
            for (int q = 0; q < 4; q++) c[mt][nt][q] = 0.f;

    const float* latp = g_lat + latoff;
    const float4* wt4 = (const float4*)g_wt + wtoff4;

    for (int j = 0; j < 9; j++) {
        const int jr = ROT[r][j];
        const int dy = j / 3 - 1, dx = j % 3 - 1;
        for (int icb = 0; icb < 8; icb++) {
            // ---- fill B smem [k32][n128] (im2col) ----
            {
                const int ic = icb * 32 + wid * 4;
#pragma unroll
                for (int i = 0; i < 4; i++) {
                    const float* src = latp + (size_t)(ic + i) * HW;
#pragma unroll
                    for (int pp = 0; pp < 4; pp++) {
                        int p = pp * 32 + lid;
                        int pg = pb * 128 + p;
                        int y = pg >> lw, x = pg & (W - 1);
                        int gy = y + dy, gx = x + dx;
                        float v = 0.f;
                        if ((unsigned)gy < (unsigned)H && (unsigned)gx < (unsigned)W)
                            v = src[gy * W + gx];
                        Bs[wid * 4 + i][p] = v;
                    }
                }
            }
            __syncthreads();
#pragma unroll
            for (int ks = 0; ks < 4; ks++) {
                const int kc = icb * 4 + ks;
                uint32_t a[2][4];
#pragma unroll
                for (int mt = 0; mt < 2; mt++) {
                    int t = (mb & 1) * 8 + warp_m * 2 + mt;
                    float4 av = wt4[((jr * 32 + kc) * 16 + t) * 32 + lid];
                    a[mt][0] = __float_as_uint(av.x);
                    a[mt][1] = __float_as_uint(av.y);
                    a[mt][2] = __float_as_uint(av.z);
                    a[mt][3] = __float_as_uint(av.w);
                }
#pragma unroll
                for (int nt = 0; nt < 8; nt++) {
                    int n = warp_n * 64 + nt * 8 + g;
                    uint32_t b0 = __float_as_uint(Bs[ks * 8 + tig][n]);
                    uint32_t b1 = __float_as_uint(Bs[ks * 8 + tig + 4][n]);
                    mma8(c[0][nt], a[0], b0, b1);
                    mma8(c[1][nt], a[1], b0, b1);
                }
            }
            __syncthreads();
        }
    }

    // ---- epilogue: bias + BN + relu -> feas ----
    float* fp = g_feas + feoff + (size_t)(r * 256 + oc0) * HW + pb * 128;
#pragma unroll
    for (int mt = 0; mt < 2; mt++) {
        int m_lo = warp_m * 32 + mt * 16 + g;
        int m_hi = m_lo + 8;
        int oc_lo = oc0 + m_lo, oc_hi = oc0 + m_hi;
        float sc_lo = bng[r * 256 + oc_lo] * rsqrtf(bnv[r * 256 + oc_lo] + BN_EPS);
        float sh_lo = bnb[r * 256 + oc_lo] + (bias[oc_lo] - bnm[r * 256 + oc_lo]) * sc_lo;
        float sc_hi = bng[r * 256 + oc_hi] * rsqrtf(bnv[r * 256 + oc_hi] + BN_EPS);
        float sh_hi = bnb[r * 256 + oc_hi] + (bias[oc_hi] - bnm[r * 256 + oc_hi]) * sc_hi;
#pragma unroll
        for (int nt = 0; nt < 8; nt++) {
            int col = warp_n * 64 + nt * 8 + 2 * tig;
            float2 vlo, vhi;
            vlo.x = fmaxf(fmaf(c[mt][nt][0], sc_lo, sh_lo), 0.f);
            vlo.y = fmaxf(fmaf(c[mt][nt][1], sc_lo, sh_lo), 0.f);
            vhi.x = fmaxf(fmaf(c[mt][nt][2], sc_hi, sh_hi), 0.f);
            vhi.y = fmaxf(fmaf(c[mt][nt][3], sc_hi, sh_hi), 0.f);
            *(float2*)(fp + (size_t)m_lo * HW + col) = vlo;
            *(float2*)(fp + (size_t)m_hi * HW + col) = vhi;
        }
    }
}

// ---------------- fea_s = mean over (branch-sum, H, W) ----------------
__global__ void reduce_fsum(int feoff, int HW, float inv, int outoff)
{
    int c = blockIdx.x;
    const float* f = g_feas + feoff;
    float s = 0.f;
    for (int r = 0; r < 5; r++) {
        const float* p = f + ((size_t)(r * 256 + c)) * HW;
        for (int i = threadIdx.x; i < HW; i += blockDim.x) s += p[i];
    }
    __shared__ float sm[256];
    sm[threadIdx.x] = s;
    __syncthreads();
    for (int o = 128; o > 0; o >>= 1) {
        if (threadIdx.x < o) sm[threadIdx.x] += sm[threadIdx.x + o];
        __syncthreads();
    }
    if (threadIdx.x == 0) g_fsum[outoff + c] = sm[0] * inv;
}

// ---------------- fea_z = fc_w @ fea_s + fc_b ----------------
__global__ void fz_kernel(const float* __restrict__ fcw, const float* __restrict__ fcb,
                          int fsoff, int fzoff)
{
    int g = threadIdx.x >> 4;
    int lane = threadIdx.x & 15;
    int d = blockIdx.x * 16 + g;
    float s = 0.f;
    for (int c = lane; c < 256; c += 16) s += fcw[d * 256 + c] * g_fsum[fsoff + c];
#pragma unroll
    for (int o = 8; o > 0; o >>= 1) s += __shfl_down_sync(0xffffffffu, s, o, 16);
    if (lane == 0) g_fz[fzoff + d] = s + fcb[d];
}

// ---------------- att = softmax_m(fcs_w @ fea_z + fcs_b) ----------------
__global__ void att_kernel(const float* __restrict__ fcsw, const float* __restrict__ fcsb,
                           int fzoff, int attoff)
{
    __shared__ float fz[128];
    if (threadIdx.x < 128) fz[threadIdx.x] = g_fz[fzoff + threadIdx.x];
    __syncthreads();
    int cl = threadIdx.x >> 5;
    int lane = threadIdx.x & 31;
    int c = blockIdx.x * 8 + cl;
    float lg[5];
#pragma unroll
    for (int m = 0; m < 5; m++) {
        float s = 0.f;
#pragma unroll
        for (int i = 0; i < 4; i++) {
            int d = lane + i * 32;
            s += fz[d] * fcsw[((m * 256 + c) * 128) + d];
        }
#pragma unroll
        for (int o = 16; o > 0; o >>= 1) s += __shfl_down_sync(0xffffffffu, s, o);
        lg[m] = s;
    }
    if (lane == 0) {
        float mx = -1e30f;
#pragma unroll
        for (int m = 0; m < 5; m++) {
            lg[m] += fcsb[m * 256 + c];
            mx = fmaxf(mx, lg[m]);
        }
        float den = 0.f;
#pragma unroll
        for (int m = 0; m < 5; m++) { lg[m] = expf(lg[m] - mx); den += lg[m]; }
        float inv = 1.f / den;
#pragma unroll
        for (int m = 0; m < 5; m++) g_att[attoff + m * 256 + c] = lg[m] * inv;
    }
}

// ---------------- out = sum_m feas[m] * att[m] ----------------
__global__ void wsum_kernel(int feoff, int attoff, float* __restrict__ out, int HW)
{
    int i4 = blockIdx.x * blockDim.x + threadIdx.x;
    int n4 = (256 * HW) >> 2;
    if (i4 >= n4) return;
    int hw4 = HW >> 2;
    int c = i4 / hw4;
    int p = i4 - c * hw4;
    const float4* f = (const float4*)(g_feas + feoff);
    float4 acc = make_float4(0.f, 0.f, 0.f, 0.f);
#pragma unroll
    for (int m = 0; m < 5; m++) {
        float a = g_att[attoff + m * 256 + c];
        float4 v = f[((size_t)(m * 256 + c)) * hw4 + p];
        acc.x = fmaf(a, v.x, acc.x);
        acc.y = fmaf(a, v.y, acc.y);
        acc.z = fmaf(a, v.z, acc.z);
        acc.w = fmaf(a, v.w, acc.w);
    }
    ((float4*)out)[i4] = acc;
}

// ---------------- launch ----------------
extern "C" void kernel_launch(void* const* d_in, const int* in_sizes, int n_in,
                              void* d_out, int out_size)
{
    const float *x[4], *lw[4];
    if (in_sizes[1] == 65536) {           // interleaved: x0,lw0,x1,lw1,...
        for (int i = 0; i < 4; i++) {
            x[i]  = (const float*)d_in[2 * i];
            lw[i] = (const float*)d_in[2 * i + 1];
        }
    } else {                              // grouped: x0..x3, lw0..lw3
        for (int i = 0; i < 4; i++) {
            x[i]  = (const float*)d_in[i];
            lw[i] = (const float*)d_in[4 + i];
        }
    }
    const float* lb   = (const float*)d_in[8];
    const float* aacw = (const float*)d_in[9];
    const float* aacb = (const float*)d_in[10];
    const float* bng  = (const float*)d_in[11];
    const float* bnb  = (const float*)d_in[12];
    const float* bnm  = (const float*)d_in[13];
    const float* bnv  = (const float*)d_in[14];
    const float* fcw  = (const float*)d_in[15];
    const float* fcb  = (const float*)d_in[16];
    const float* fcsw = (const float*)d_in[17];
    const float* fcsb = (const float*)d_in[18];
    float* out = (float*)d_out;

    static const int Hs[4]      = {128, 64, 32, 16};
    static const int lws_[4]    = {7, 6, 5, 4};  // log2 W
    static const int cins[4]    = {256, 512, 1024, 2048};
    static const int S[4]       = {1, 2, 4, 8};
    static const int latOff[4]  = {0, 4194304, 5242880, 5505024};
    static const int feasOff[4] = {0, 20971520, 26214400, 27525120};

    // 0) weight transpose to tf32 fragment layout (independent)
    wt_transpose<<<9216, 256>>>(aacw);

    // 1) lateral 1x1 convs (split-K for small-N levels)
    float* g_lat_p;
    cudaGetSymbolAddress((void**)&g_lat_p, g_lat);
    float* g_part_p;
    cudaGetSymbolAddress((void**)&g_part_p, g_part);
    for (int i = 0; i < 4; i++) {
        int N = Hs[i] * Hs[i];
        int s = S[i];
        dim3 g(N / 64, 4, s);
        float* outp = (s == 1) ? (g_lat_p + latOff[i]) : g_part_p;
        lateral_gemm<<<g, 256>>>(lw[i], x[i], lb + i * 256, outp,
                                 cins[i], cins[i] / s, N, s == 1 ? 1 : 0);
        if (s > 1)
            reduce_part<<<(256 * N + 255) / 256, 256>>>(latOff[i], lb + i * 256, N, s);
    }
    // 2) top-down pathway
    for (int i = 3; i >= 1; i--) {
        int Hd = Hs[i - 1];
        int n4 = 256 * Hd * Hd / 4;
        up_add<<<(n4 + 255) / 256, 256>>>(latOff[i - 1], latOff[i], Hd, Hd);
    }
    // 2b) round lat to tf32 (RN)
    round_lat<<<5440, 256>>>();

    // 3) per-level AAC conv (mma.sync tf32) + SK fusion
    for (int i = 0; i < 4; i++) {
        int H = Hs[i];
        int HW = H * H;
        dim3 g(HW / 128, 10);
        conv_aac_mma<<<g, 256>>>(aacb + i * 256,
                                 bng + i * 1280, bnb + i * 1280,
                                 bnm + i * 1280, bnv + i * 1280,
                                 latOff[i], feasOff[i], i * 147456,
                                 H, H, lws_[i]);
        reduce_fsum<<<256, 256>>>(feasOff[i], HW, 1.f / (float)HW, i * 256);
        fz_kernel<<<8, 256>>>(fcw + i * 128 * 256, fcb + i * 128, i * 256, i * 128);
        att_kernel<<<32, 256>>>(fcsw + i * 5 * 256 * 128, fcsb + i * 5 * 256,
                                i * 128, i * 1280);
        int n4 = 256 * HW / 4;
        wsum_kernel<<<(n4 + 255) / 256, 256>>>(feasOff[i], i * 1280, out + latOff[i], HW);
    }
    (void)n_in; (void)out_size;
}

// round 5
// speedup vs baseline: 2.5664x; 1.6443x over previous
#include <cuda_runtime.h>
#include <cstdint>
#include <math.h>

// ---------------- scratch (device globals; no allocation) ----------------
__device__ float g_lat[5570560];      // 4 levels of (256,H,W)
__device__ float g_feas[27852800];    // 4 levels of (5,256,H,W)
__device__ float g_wt[2359296];       // tf32 weights, mma-fragment order
__device__ float g_part[2097152];     // split-K partials
__device__ float g_fsum[4 * 256];
__device__ float g_fz[4 * 128];
__device__ float g_att[4 * 5 * 256];

#define BN_EPS 1e-5f

__device__ __forceinline__ float tf32r(float x) {
    uint32_t u;
    asm("cvt.rn.tf32.f32 %0, %1;" : "=r"(u) : "f"(x));
    return __uint_as_float(u);
}

__device__ __forceinline__ void mma8(float* c, const uint32_t* a,
                                     uint32_t b0, uint32_t b1) {
    asm volatile(
        "mma.sync.aligned.m16n8k8.row.col.f32.tf32.tf32.f32 "
        "{%0,%1,%2,%3}, {%4,%5,%6,%7}, {%8,%9}, {%0,%1,%2,%3};"
        : "+f"(c[0]), "+f"(c[1]), "+f"(c[2]), "+f"(c[3])
        : "r"(a[0]), "r"(a[1]), "r"(a[2]), "r"(a[3]), "r"(b0), "r"(b1));
}

// ---------------- weight transpose + tf32 round (fragment order) ----------
// For j, kc(32 k8-chunks), t(16 m16-tiles), lane(32), q(4):
//   oc = t*16 + (lane>>2) + 8*(q&1);  ic = kc*8 + (lane&3) + 4*(q>>1)
__global__ void wt_transpose(const float* __restrict__ aacw)
{
    int idx = blockIdx.x * 256 + threadIdx.x;
    if (idx >= 2359296) return;
    int q = idx & 3;
    int l = (idx >> 2) & 31;
    int t = (idx >> 7) & 15;
    int kc = (idx >> 11) & 31;
    int lj = idx >> 16;           // lvl*9 + j
    int j = lj % 9, lvl = lj / 9;
    int oc = t * 16 + (l >> 2) + 8 * (q & 1);
    int ic = kc * 8 + (l & 3) + 4 * (q >> 1);
    g_wt[idx] = tf32r(aacw[((lvl * 256 + oc) * 256 + ic) * 9 + j]);
}

// ---------------- round lat to tf32 (RN) in place ----------------
__global__ void round_lat()
{
    int i = blockIdx.x * 256 + threadIdx.x;
    if (i >= 1392640) return;
    float4* p = (float4*)g_lat + i;
    float4 v = *p;
    v.x = tf32r(v.x); v.y = tf32r(v.y); v.z = tf32r(v.z); v.w = tf32r(v.w);
    *p = v;
}

// ---------------- lateral 1x1 conv as tiled SGEMM (split-K capable) -------
__global__ __launch_bounds__(256)
void lateral_gemm(const float* __restrict__ A, const float* __restrict__ X,
                  const float* __restrict__ bias, float* __restrict__ outp,
                  int K, int kLen, int N, int addbias)
{
    __shared__ float As[16][64];
    __shared__ float Bs[16][64];
    const int tx = threadIdx.x & 15;
    const int ty = threadIdx.x >> 4;
    const int row0 = blockIdx.y * 64;
    const int col0 = blockIdx.x * 64;
    const int kb = blockIdx.z * kLen;

    float acc[4][4];
#pragma unroll
    for (int i = 0; i < 4; i++)
#pragma unroll
        for (int j = 0; j < 4; j++) acc[i][j] = 0.f;

    for (int k0 = kb; k0 < kb + kLen; k0 += 16) {
#pragma unroll
        for (int i = 0; i < 4; i++) {
            int idx = threadIdx.x + i * 256;
            int r = idx >> 4, k = idx & 15;
            As[k][r] = A[(row0 + r) * K + k0 + k];
        }
#pragma unroll
        for (int i = 0; i < 4; i++) {
            int idx = threadIdx.x + i * 256;
            int k = idx >> 6, c = idx & 63;
            Bs[k][c] = X[(k0 + k) * N + col0 + c];
        }
        __syncthreads();
#pragma unroll
        for (int k = 0; k < 16; k++) {
            float4 a4 = *(const float4*)&As[k][ty * 4];
            float4 b4 = *(const float4*)&Bs[k][tx * 4];
            float a[4] = {a4.x, a4.y, a4.z, a4.w};
            float b[4] = {b4.x, b4.y, b4.z, b4.w};
#pragma unroll
            for (int i = 0; i < 4; i++)
#pragma unroll
                for (int j = 0; j < 4; j++) acc[i][j] = fmaf(a[i], b[j], acc[i][j]);
        }
        __syncthreads();
    }
    float* out = outp + (size_t)blockIdx.z * 256 * N;
#pragma unroll
    for (int i = 0; i < 4; i++) {
        float bv = addbias ? bias[row0 + ty * 4 + i] : 0.f;
#pragma unroll
        for (int j = 0; j < 4; j++)
            out[(row0 + ty * 4 + i) * N + col0 + tx * 4 + j] = acc[i][j] + bv;
    }
}

// reduce split-K partials + bias -> g_lat
__global__ void reduce_part(int latoff, const float* __restrict__ lb, int N, int S)
{
    int idx = blockIdx.x * 256 + threadIdx.x;
    if (idx >= 256 * N) return;
    float s = lb[idx / N];
    for (int z = 0; z < S; z++) s += g_part[(size_t)z * 256 * N + idx];
    g_lat[latoff + idx] = s;
}

// ---------------- nearest 2x upsample-add (dst += up2(src)) ----------------
__global__ void up_add(int dstoff, int srcoff, int H, int W)
{
    int i4 = blockIdx.x * blockDim.x + threadIdx.x;
    int HW = H * W;
    int n4 = (256 * HW) >> 2;
    if (i4 >= n4) return;
    int hw4 = HW >> 2;
    int c = i4 / hw4;
    int rem = i4 - c * hw4;
    int w4 = W >> 2;
    int y = rem / w4;
    int x4 = rem - y * w4;
    int H2 = H >> 1, W2 = W >> 1;
    int selem = c * H2 * W2 + (y >> 1) * W2 + (x4 << 1);
    float2 sv = *(const float2*)(g_lat + srcoff + selem);
    float4* d = (float4*)(g_lat + dstoff) + i4;
    float4 dv = *d;
    dv.x += sv.x; dv.y += sv.x; dv.z += sv.y; dv.w += sv.y;
    *d = dv;
}

// ---------------- AAC conv via mma.sync tf32 implicit GEMM ----------------
// grid: (HW/128, 10). mb -> branch r = mb/2, oc0 = (mb&1)*128.
// Pixel tile = 16x8. Per 32-ic chunk: load haloed input tile [32][10][18]
// (padded stride 184) ONCE, then run all 9 taps x 4 k8-steps from smem.
__global__ __launch_bounds__(256, 2)
void conv_aac_mma(const float* __restrict__ bias,
                  const float* __restrict__ bng, const float* __restrict__ bnb,
                  const float* __restrict__ bnm, const float* __restrict__ bnv,
                  int latoff, int feoff, int wtoff4, int H, int W)
{
    constexpr int ROT[5][9] = {
        {0, 1, 2, 3, 4, 5, 6, 7, 8},
        {3, 0, 1, 6, 4, 2, 7, 8, 5},
        {6, 3, 0, 7, 4, 1, 8, 5, 2},
        {7, 6, 3, 8, 4, 0, 5, 2, 1},
        {8, 7, 6, 5, 4, 3, 2, 1, 0}};

    __shared__ float s_in[32 * 184];   // per-ic stride 184 (10x18 used)

    const int tid = threadIdx.x;
    const int wid = tid >> 5, lid = tid & 31;
    const int g = lid >> 2, tig = lid & 3;
    const int warp_m = wid & 3, warp_n = wid >> 2;
    const int HW = H * W;
    const int tiles_x = W >> 4;
    const int pb = blockIdx.x;
    const int tbx = pb % tiles_x, tby = pb / tiles_x;
    const int tx0 = tbx << 4, ty0 = tby << 3;
    const int mb = blockIdx.y;
    const int r = mb >> 1;
    const int oc0 = (mb & 1) << 7;

    float c[2][8][4];
#pragma unroll
    for (int mt = 0; mt < 2; mt++)
#pragma unroll
        for (int nt = 0; nt < 8; nt++)
#pragma unroll
            for (int q = 0; q < 4; q++) c[mt][nt][q] = 0.f;

    const float* latp = g_lat + latoff;
    const float4* wt4 = (const float4*)g_wt + wtoff4;

    for (int icb = 0; icb < 8; icb++) {
        __syncthreads();
        // ---- fill haloed input tile: 32 ic x 10 x 18 ----
        for (int e = tid; e < 5760; e += 256) {
            int ic = e / 180;
            int sp = e - ic * 180;
            int yy = sp / 18, xx = sp - yy * 18;
            int gy = ty0 + yy - 1, gx = tx0 + xx - 1;
            float v = 0.f;
            if ((unsigned)gy < (unsigned)H && (unsigned)gx < (unsigned)W)
                v = latp[(size_t)(icb * 32 + ic) * HW + gy * W + gx];
            s_in[ic * 184 + yy * 18 + xx] = v;
        }
        __syncthreads();

        for (int j = 0; j < 9; j++) {
            const int jr = ROT[r][j];
            const int dy = j / 3, dx = j % 3;   // halo coords: +dy, +dx
#pragma unroll
            for (int ks = 0; ks < 4; ks++) {
                const int kc = icb * 4 + ks;
                uint32_t a[2][4];
#pragma unroll
                for (int mt = 0; mt < 2; mt++) {
                    int t = (mb & 1) * 8 + warp_m * 2 + mt;
                    float4 av = wt4[((jr * 32 + kc) * 16 + t) * 32 + lid];
                    a[mt][0] = __float_as_uint(av.x);
                    a[mt][1] = __float_as_uint(av.y);
                    a[mt][2] = __float_as_uint(av.z);
                    a[mt][3] = __float_as_uint(av.w);
                }
                const int base_lo = (ks * 8 + tig) * 184;
                const int base_hi = base_lo + 4 * 184;
#pragma unroll
                for (int nt = 0; nt < 8; nt++) {
                    int n = warp_n * 64 + nt * 8 + g;
                    int yl = n >> 4, xl = n & 15;
                    int off = (yl + dy) * 18 + xl + dx;
                    uint32_t b0 = __float_as_uint(s_in[base_lo + off]);
                    uint32_t b1 = __float_as_uint(s_in[base_hi + off]);
                    mma8(c[0][nt], a[0], b0, b1);
                    mma8(c[1][nt], a[1], b0, b1);
                }
            }
        }
    }

    // ---- epilogue: bias + BN + relu -> feas ----
    float* fp = g_feas + feoff + (size_t)(r * 256 + oc0) * HW + ty0 * W + tx0;
#pragma unroll
    for (int mt = 0; mt < 2; mt++) {
        int m_lo = warp_m * 32 + mt * 16 + g;
        int m_hi = m_lo + 8;
        int oc_lo = oc0 + m_lo, oc_hi = oc0 + m_hi;
        float sc_lo = bng[r * 256 + oc_lo] * rsqrtf(bnv[r * 256 + oc_lo] + BN_EPS);
        float sh_lo = bnb[r * 256 + oc_lo] + (bias[oc_lo] - bnm[r * 256 + oc_lo]) * sc_lo;
        float sc_hi = bng[r * 256 + oc_hi] * rsqrtf(bnv[r * 256 + oc_hi] + BN_EPS);
        float sh_hi = bnb[r * 256 + oc_hi] + (bias[oc_hi] - bnm[r * 256 + oc_hi]) * sc_hi;
#pragma unroll
        for (int nt = 0; nt < 8; nt++) {
            int col = warp_n * 64 + nt * 8 + 2 * tig;
            int yl = col >> 4, xl = col & 15;
            float2 vlo, vhi;
            vlo.x = fmaxf(fmaf(c[mt][nt][0], sc_lo, sh_lo), 0.f);
            vlo.y = fmaxf(fmaf(c[mt][nt][1], sc_lo, sh_lo), 0.f);
            vhi.x = fmaxf(fmaf(c[mt][nt][2], sc_hi, sh_hi), 0.f);
            vhi.y = fmaxf(fmaf(c[mt][nt][3], sc_hi, sh_hi), 0.f);
            *(float2*)(fp + (size_t)m_lo * HW + yl * W + xl) = vlo;
            *(float2*)(fp + (size_t)m_hi * HW + yl * W + xl) = vhi;
        }
    }
}

// ---------------- fea_s = mean over (branch-sum, H, W) ----------------
__global__ void reduce_fsum(int feoff, int HW, float inv, int outoff)
{
    int c = blockIdx.x;
    const float* f = g_feas + feoff;
    float s = 0.f;
    for (int r = 0; r < 5; r++) {
        const float* p = f + ((size_t)(r * 256 + c)) * HW;
        for (int i = threadIdx.x; i < HW; i += blockDim.x) s += p[i];
    }
    __shared__ float sm[256];
    sm[threadIdx.x] = s;
    __syncthreads();
    for (int o = 128; o > 0; o >>= 1) {
        if (threadIdx.x < o) sm[threadIdx.x] += sm[threadIdx.x + o];
        __syncthreads();
    }
    if (threadIdx.x == 0) g_fsum[outoff + c] = sm[0] * inv;
}

// ---------------- fea_z = fc_w @ fea_s + fc_b ----------------
__global__ void fz_kernel(const float* __restrict__ fcw, const float* __restrict__ fcb,
                          int fsoff, int fzoff)
{
    int g = threadIdx.x >> 4;
    int lane = threadIdx.x & 15;
    int d = blockIdx.x * 16 + g;
    float s = 0.f;
    for (int c = lane; c < 256; c += 16) s += fcw[d * 256 + c] * g_fsum[fsoff + c];
#pragma unroll
    for (int o = 8; o > 0; o >>= 1) s += __shfl_down_sync(0xffffffffu, s, o, 16);
    if (lane == 0) g_fz[fzoff + d] = s + fcb[d];
}

// ---------------- att = softmax_m(fcs_w @ fea_z + fcs_b) ----------------
__global__ void att_kernel(const float* __restrict__ fcsw, const float* __restrict__ fcsb,
                           int fzoff, int attoff)
{
    __shared__ float fz[128];
    if (threadIdx.x < 128) fz[threadIdx.x] = g_fz[fzoff + threadIdx.x];
    __syncthreads();
    int cl = threadIdx.x >> 5;
    int lane = threadIdx.x & 31;
    int c = blockIdx.x * 8 + cl;
    float lg[5];
#pragma unroll
    for (int m = 0; m < 5; m++) {
        float s = 0.f;
#pragma unroll
        for (int i = 0; i < 4; i++) {
            int d = lane + i * 32;
            s += fz[d] * fcsw[((m * 256 + c) * 128) + d];
        }
#pragma unroll
        for (int o = 16; o > 0; o >>= 1) s += __shfl_down_sync(0xffffffffu, s, o);
        lg[m] = s;
    }
    if (lane == 0) {
        float mx = -1e30f;
#pragma unroll
        for (int m = 0; m < 5; m++) {
            lg[m] += fcsb[m * 256 + c];
            mx = fmaxf(mx, lg[m]);
        }
        float den = 0.f;
#pragma unroll
        for (int m = 0; m < 5; m++) { lg[m] = expf(lg[m] - mx); den += lg[m]; }
        float inv = 1.f / den;
#pragma unroll
        for (int m = 0; m < 5; m++) g_att[attoff + m * 256 + c] = lg[m] * inv;
    }
}

// ---------------- out = sum_m feas[m] * att[m] ----------------
__global__ void wsum_kernel(int feoff, int attoff, float* __restrict__ out, int HW)
{
    int i4 = blockIdx.x * blockDim.x + threadIdx.x;
    int n4 = (256 * HW) >> 2;
    if (i4 >= n4) return;
    int hw4 = HW >> 2;
    int c = i4 / hw4;
    int p = i4 - c * hw4;
    const float4* f = (const float4*)(g_feas + feoff);
    float4 acc = make_float4(0.f, 0.f, 0.f, 0.f);
#pragma unroll
    for (int m = 0; m < 5; m++) {
        float a = g_att[attoff + m * 256 + c];
        float4 v = f[((size_t)(m * 256 + c)) * hw4 + p];
        acc.x = fmaf(a, v.x, acc.x);
        acc.y = fmaf(a, v.y, acc.y);
        acc.z = fmaf(a, v.z, acc.z);
        acc.w = fmaf(a, v.w, acc.w);
    }
    ((float4*)out)[i4] = acc;
}

// ---------------- launch ----------------
extern "C" void kernel_launch(void* const* d_in, const int* in_sizes, int n_in,
                              void* d_out, int out_size)
{
    const float *x[4], *lw[4];
    if (in_sizes[1] == 65536) {           // interleaved: x0,lw0,x1,lw1,...
        for (int i = 0; i < 4; i++) {
            x[i]  = (const float*)d_in[2 * i];
            lw[i] = (const float*)d_in[2 * i + 1];
        }
    } else {                              // grouped: x0..x3, lw0..lw3
        for (int i = 0; i < 4; i++) {
            x[i]  = (const float*)d_in[i];
            lw[i] = (const float*)d_in[4 + i];
        }
    }
    const float* lb   = (const float*)d_in[8];
    const float* aacw = (const float*)d_in[9];
    const float* aacb = (const float*)d_in[10];
    const float* bng  = (const float*)d_in[11];
    const float* bnb  = (const float*)d_in[12];
    const float* bnm  = (const float*)d_in[13];
    const float* bnv  = (const float*)d_in[14];
    const float* fcw  = (const float*)d_in[15];
    const float* fcb  = (const float*)d_in[16];
    const float* fcsw = (const float*)d_in[17];
    const float* fcsb = (const float*)d_in[18];
    float* out = (float*)d_out;

    static const int Hs[4]      = {128, 64, 32, 16};
    static const int cins[4]    = {256, 512, 1024, 2048};
    static const int S[4]       = {1, 2, 4, 8};
    static const int latOff[4]  = {0, 4194304, 5242880, 5505024};
    static const int feasOff[4] = {0, 20971520, 26214400, 27525120};

    // 0) weight transpose to tf32 fragment layout (independent)
    wt_transpose<<<9216, 256>>>(aacw);

    // 1) lateral 1x1 convs (split-K for small-N levels)
    float* g_lat_p;
    cudaGetSymbolAddress((void**)&g_lat_p, g_lat);
    float* g_part_p;
    cudaGetSymbolAddress((void**)&g_part_p, g_part);
    for (int i = 0; i < 4; i++) {
        int N = Hs[i] * Hs[i];
        int s = S[i];
        dim3 g(N / 64, 4, s);
        float* outp = (s == 1) ? (g_lat_p + latOff[i]) : g_part_p;
        lateral_gemm<<<g, 256>>>(lw[i], x[i], lb + i * 256, outp,
                                 cins[i], cins[i] / s, N, s == 1 ? 1 : 0);
        if (s > 1)
            reduce_part<<<(256 * N + 255) / 256, 256>>>(latOff[i], lb + i * 256, N, s);
    }
    // 2) top-down pathway
    for (int i = 3; i >= 1; i--) {
        int Hd = Hs[i - 1];
        int n4 = 256 * Hd * Hd / 4;
        up_add<<<(n4 + 255) / 256, 256>>>(latOff[i - 1], latOff[i], Hd, Hd);
    }
    // 2b) round lat to tf32 (RN)
    round_lat<<<5440, 256>>>();

    // 3) per-level AAC conv (mma.sync tf32) + SK fusion
    for (int i = 0; i < 4; i++) {
        int H = Hs[i];
        int HW = H * H;
        dim3 g(HW / 128, 10);
        conv_aac_mma<<<g, 256>>>(aacb + i * 256,
                                 bng + i * 1280, bnb + i * 1280,
                                 bnm + i * 1280, bnv + i * 1280,
                                 latOff[i], feasOff[i], i * 147456,
                                 H, H);
        reduce_fsum<<<256, 256>>>(feasOff[i], HW, 1.f / (float)HW, i * 256);
        fz_kernel<<<8, 256>>>(fcw + i * 128 * 256, fcb + i * 128, i * 256, i * 128);
        att_kernel<<<32, 256>>>(fcsw + i * 5 * 256 * 128, fcsb + i * 5 * 256,
                                i * 128, i * 1280);
        int n4 = 256 * HW / 4;
        wsum_kernel<<<(n4 + 255) / 256, 256>>>(feasOff[i], i * 1280, out + latOff[i], HW);
    }
    (void)n_in; (void)out_size;
}

// round 6
// speedup vs baseline: 3.2700x; 1.2742x over previous
#include <cuda_runtime.h>
#include <cstdint>
#include <math.h>

// ---------------- scratch (device globals; no allocation) ----------------
__device__ float g_lat[5570560];      // 4 levels of (256,H,W)
__device__ float g_feas[27852800];    // 4 levels of (5,256,H,W)
__device__ float g_wt[2359296];       // tf32 weights, mma-fragment order
__device__ float g_part[2097152];     // split-K partials
__device__ float g_fsum[4 * 256];
__device__ float g_fz[4 * 128];
__device__ float g_att[4 * 5 * 256];

#define BN_EPS 1e-5f

__device__ __forceinline__ float tf32r(float x) {
    uint32_t u;
    asm("cvt.rn.tf32.f32 %0, %1;" : "=r"(u) : "f"(x));
    return __uint_as_float(u);
}
__device__ __forceinline__ uint32_t smem_u32(const void* p) {
    uint32_t a;
    asm("{ .reg .u64 t; cvta.to.shared.u64 t, %1; cvt.u32.u64 %0, t; }" : "=r"(a) : "l"(p));
    return a;
}
#define CP_ASYNC4(dst, src, sz) \
    asm volatile("cp.async.ca.shared.global [%0], [%1], 4, %2;" \
                 :: "r"(dst), "l"(src), "r"(sz) : "memory")
#define CP_COMMIT() asm volatile("cp.async.commit_group;" ::: "memory")
#define CP_WAIT0()  asm volatile("cp.async.wait_group 0;" ::: "memory")

__device__ __forceinline__ void mma8(float* c, const uint32_t* a,
                                     uint32_t b0, uint32_t b1) {
    asm volatile(
        "mma.sync.aligned.m16n8k8.row.col.f32.tf32.tf32.f32 "
        "{%0,%1,%2,%3}, {%4,%5,%6,%7}, {%8,%9}, {%0,%1,%2,%3};"
        : "+f"(c[0]), "+f"(c[1]), "+f"(c[2]), "+f"(c[3])
        : "r"(a[0]), "r"(a[1]), "r"(a[2]), "r"(a[3]), "r"(b0), "r"(b1));
}

// ---------------- weight transpose + tf32 round (fragment order) ----------
__global__ void wt_transpose(const float* __restrict__ aacw)
{
    int idx = blockIdx.x * 256 + threadIdx.x;
    if (idx >= 2359296) return;
    int q = idx & 3;
    int l = (idx >> 2) & 31;
    int t = (idx >> 7) & 15;
    int kc = (idx >> 11) & 31;
    int lj = idx >> 16;           // lvl*9 + j
    int j = lj % 9, lvl = lj / 9;
    int oc = t * 16 + (l >> 2) + 8 * (q & 1);
    int ic = kc * 8 + (l & 3) + 4 * (q >> 1);
    g_wt[idx] = tf32r(aacw[((lvl * 256 + oc) * 256 + ic) * 9 + j]);
}

// ---------------- round lat to tf32 (RN) in place ----------------
__global__ void round_lat()
{
    int i = blockIdx.x * 256 + threadIdx.x;
    if (i >= 1392640) return;
    float4* p = (float4*)g_lat + i;
    float4 v = *p;
    v.x = tf32r(v.x); v.y = tf32r(v.y); v.z = tf32r(v.z); v.w = tf32r(v.w);
    *p = v;
}

// ---------------- lateral 1x1 conv as tiled SGEMM (split-K capable) -------
__global__ __launch_bounds__(256)
void lateral_gemm(const float* __restrict__ A, const float* __restrict__ X,
                  const float* __restrict__ bias, float* __restrict__ outp,
                  int K, int kLen, int N, int addbias)
{
    __shared__ float As[16][64];
    __shared__ float Bs[16][64];
    const int tx = threadIdx.x & 15;
    const int ty = threadIdx.x >> 4;
    const int row0 = blockIdx.y * 64;
    const int col0 = blockIdx.x * 64;
    const int kb = blockIdx.z * kLen;

    float acc[4][4];
#pragma unroll
    for (int i = 0; i < 4; i++)
#pragma unroll
        for (int j = 0; j < 4; j++) acc[i][j] = 0.f;

    for (int k0 = kb; k0 < kb + kLen; k0 += 16) {
#pragma unroll
        for (int i = 0; i < 4; i++) {
            int idx = threadIdx.x + i * 256;
            int r = idx >> 4, k = idx & 15;
            As[k][r] = A[(row0 + r) * K + k0 + k];
        }
#pragma unroll
        for (int i = 0; i < 4; i++) {
            int idx = threadIdx.x + i * 256;
            int k = idx >> 6, c = idx & 63;
            Bs[k][c] = X[(k0 + k) * N + col0 + c];
        }
        __syncthreads();
#pragma unroll
        for (int k = 0; k < 16; k++) {
            float4 a4 = *(const float4*)&As[k][ty * 4];
            float4 b4 = *(const float4*)&Bs[k][tx * 4];
            float a[4] = {a4.x, a4.y, a4.z, a4.w};
            float b[4] = {b4.x, b4.y, b4.z, b4.w};
#pragma unroll
            for (int i = 0; i < 4; i++)
#pragma unroll
                for (int j = 0; j < 4; j++) acc[i][j] = fmaf(a[i], b[j], acc[i][j]);
        }
        __syncthreads();
    }
    float* out = outp + (size_t)blockIdx.z * 256 * N;
#pragma unroll
    for (int i = 0; i < 4; i++) {
        float bv = addbias ? bias[row0 + ty * 4 + i] : 0.f;
#pragma unroll
        for (int j = 0; j < 4; j++)
            out[(row0 + ty * 4 + i) * N + col0 + tx * 4 + j] = acc[i][j] + bv;
    }
}

// reduce split-K partials + bias -> g_lat
__global__ void reduce_part(int latoff, const float* __restrict__ lb, int N, int S)
{
    int idx = blockIdx.x * 256 + threadIdx.x;
    if (idx >= 256 * N) return;
    float s = lb[idx / N];
    for (int z = 0; z < S; z++) s += g_part[(size_t)z * 256 * N + idx];
    g_lat[latoff + idx] = s;
}

// ---------------- nearest 2x upsample-add (dst += up2(src)) ----------------
__global__ void up_add(int dstoff, int srcoff, int H, int W)
{
    int i4 = blockIdx.x * blockDim.x + threadIdx.x;
    int HW = H * W;
    int n4 = (256 * HW) >> 2;
    if (i4 >= n4) return;
    int hw4 = HW >> 2;
    int c = i4 / hw4;
    int rem = i4 - c * hw4;
    int w4 = W >> 2;
    int y = rem / w4;
    int x4 = rem - y * w4;
    int H2 = H >> 1, W2 = W >> 1;
    int selem = c * H2 * W2 + (y >> 1) * W2 + (x4 << 1);
    float2 sv = *(const float2*)(g_lat + srcoff + selem);
    float4* d = (float4*)(g_lat + dstoff) + i4;
    float4 dv = *d;
    dv.x += sv.x; dv.y += sv.x; dv.z += sv.y; dv.w += sv.y;
    *d = dv;
}

// ---------------- AAC conv via mma.sync tf32, ALL LEVELS, cp.async 2-buf --
// grid: (170, 10). blockIdx.x -> (level, pixel tile 16x8); mb -> (branch, oc half)
__global__ __launch_bounds__(256, 2)
void conv_aac_all(const float* __restrict__ bias4,
                  const float* __restrict__ bng4, const float* __restrict__ bnb4,
                  const float* __restrict__ bnm4, const float* __restrict__ bnv4)
{
    constexpr int ROT[5][9] = {
        {0, 1, 2, 3, 4, 5, 6, 7, 8},
        {3, 0, 1, 6, 4, 2, 7, 8, 5},
        {6, 3, 0, 7, 4, 1, 8, 5, 2},
        {7, 6, 3, 8, 4, 0, 5, 2, 1},
        {8, 7, 6, 5, 4, 3, 2, 1, 0}};
    constexpr int HS[4]      = {128, 64, 32, 16};
    constexpr int LATOFF[4]  = {0, 4194304, 5242880, 5505024};
    constexpr int FEOFF[4]   = {0, 20971520, 26214400, 27525120};
    constexpr int TSTART[5]  = {0, 128, 160, 168, 170};

    __shared__ float s_in[2][32 * 184];   // double-buffered haloed tiles

    const int tid = threadIdx.x;
    const int wid = tid >> 5, lid = tid & 31;
    const int g = lid >> 2, tig = lid & 3;
    const int warp_m = wid & 3, warp_n = wid >> 2;

    // decode level + tile
    int pbx = blockIdx.x;
    int lvl = 0;
    if (pbx >= TSTART[1]) lvl = (pbx >= TSTART[3]) ? 3 : ((pbx >= TSTART[2]) ? 2 : 1);
    const int tb = pbx - TSTART[lvl];
    const int H = HS[lvl], W = H;
    const int HW = H * W;
    const int tiles_x = W >> 4;
    const int tx0 = (tb % tiles_x) << 4;
    const int ty0 = (tb / tiles_x) << 3;
    const int mb = blockIdx.y;
    const int r = mb >> 1;
    const int oc0 = (mb & 1) << 7;

    const float* bias = bias4 + lvl * 256;
    const float* bng = bng4 + lvl * 1280;
    const float* bnb = bnb4 + lvl * 1280;
    const float* bnm = bnm4 + lvl * 1280;
    const float* bnv = bnv4 + lvl * 1280;
    const float* latp = g_lat + LATOFF[lvl];
    const float4* wt4 = (const float4*)g_wt + lvl * 147456;
    const uint32_t sbase = smem_u32(&s_in[0][0]);

    float c[2][8][4];
#pragma unroll
    for (int mt = 0; mt < 2; mt++)
#pragma unroll
        for (int nt = 0; nt < 8; nt++)
#pragma unroll
            for (int q = 0; q < 4; q++) c[mt][nt][q] = 0.f;

    // ---- async fill of haloed tile [32ic][10][18] into buffer b ----
    auto fill = [&](int icb, int b) {
#pragma unroll 1
        for (int e = tid; e < 5760; e += 256) {
            int ic = e / 180;
            int sp = e - ic * 180;
            int yy = sp / 18, xx = sp - yy * 18;
            int gy = ty0 + yy - 1, gx = tx0 + xx - 1;
            bool ok = ((unsigned)gy < (unsigned)H) && ((unsigned)gx < (unsigned)W);
            const float* src = latp + ((size_t)(icb * 32 + ic) * HW +
                                       (ok ? (gy * W + gx) : 0));
            uint32_t dst = sbase + (uint32_t)(b * 5888 + ic * 184 + yy * 18 + xx) * 4u;
            CP_ASYNC4(dst, src, ok ? 4u : 0u);
        }
    };

    fill(0, 0);
    CP_COMMIT();
    CP_WAIT0();
    __syncthreads();

    for (int icb = 0; icb < 8; icb++) {
        const int cur = icb & 1;
        if (icb < 7) {
            fill(icb + 1, cur ^ 1);
            CP_COMMIT();
        }
        const float* sin = &s_in[cur][0];
        for (int j = 0; j < 9; j++) {
            const int jr = ROT[r][j];
            const int dy = j / 3, dx = j % 3;
#pragma unroll
            for (int ks = 0; ks < 4; ks++) {
                const int kc = icb * 4 + ks;
                uint32_t a[2][4];
#pragma unroll
                for (int mt = 0; mt < 2; mt++) {
                    int t = (mb & 1) * 8 + warp_m * 2 + mt;
                    float4 av = wt4[((jr * 32 + kc) * 16 + t) * 32 + lid];
                    a[mt][0] = __float_as_uint(av.x);
                    a[mt][1] = __float_as_uint(av.y);
                    a[mt][2] = __float_as_uint(av.z);
                    a[mt][3] = __float_as_uint(av.w);
                }
                const int base_lo = (ks * 8 + tig) * 184;
                const int base_hi = base_lo + 4 * 184;
#pragma unroll
                for (int nt = 0; nt < 8; nt++) {
                    int n = warp_n * 64 + nt * 8 + g;
                    int yl = n >> 4, xl = n & 15;
                    int off = (yl + dy) * 18 + xl + dx;
                    uint32_t b0 = __float_as_uint(sin[base_lo + off]);
                    uint32_t b1 = __float_as_uint(sin[base_hi + off]);
                    mma8(c[0][nt], a[0], b0, b1);
                    mma8(c[1][nt], a[1], b0, b1);
                }
            }
        }
        if (icb < 7) CP_WAIT0();
        __syncthreads();
    }

    // ---- epilogue: bias + BN + relu -> feas ----
    float* fp = g_feas + FEOFF[lvl] + (size_t)(r * 256 + oc0) * HW + ty0 * W + tx0;
#pragma unroll
    for (int mt = 0; mt < 2; mt++) {
        int m_lo = warp_m * 32 + mt * 16 + g;
        int m_hi = m_lo + 8;
        int oc_lo = oc0 + m_lo, oc_hi = oc0 + m_hi;
        float sc_lo = bng[r * 256 + oc_lo] * rsqrtf(bnv[r * 256 + oc_lo] + BN_EPS);
        float sh_lo = bnb[r * 256 + oc_lo] + (bias[oc_lo] - bnm[r * 256 + oc_lo]) * sc_lo;
        float sc_hi = bng[r * 256 + oc_hi] * rsqrtf(bnv[r * 256 + oc_hi] + BN_EPS);
        float sh_hi = bnb[r * 256 + oc_hi] + (bias[oc_hi] - bnm[r * 256 + oc_hi]) * sc_hi;
#pragma unroll
        for (int nt = 0; nt < 8; nt++) {
            int col = warp_n * 64 + nt * 8 + 2 * tig;
            int yl = col >> 4, xl = col & 15;
            float2 vlo, vhi;
            vlo.x = fmaxf(fmaf(c[mt][nt][0], sc_lo, sh_lo), 0.f);
            vlo.y = fmaxf(fmaf(c[mt][nt][1], sc_lo, sh_lo), 0.f);
            vhi.x = fmaxf(fmaf(c[mt][nt][2], sc_hi, sh_hi), 0.f);
            vhi.y = fmaxf(fmaf(c[mt][nt][3], sc_hi, sh_hi), 0.f);
            *(float2*)(fp + (size_t)m_lo * HW + yl * W + xl) = vlo;
            *(float2*)(fp + (size_t)m_hi * HW + yl * W + xl) = vhi;
        }
    }
}

// ---------------- fea_s: all levels, grid (256, 4) ----------------
__global__ void reduce_fsum_all()
{
    constexpr int FEOFF[4] = {0, 20971520, 26214400, 27525120};
    constexpr int HWs[4]   = {16384, 4096, 1024, 256};
    int lvl = blockIdx.y;
    int HW = HWs[lvl];
    int c = blockIdx.x;
    const float* f = g_feas + FEOFF[lvl];
    float s = 0.f;
    for (int r = 0; r < 5; r++) {
        const float* p = f + ((size_t)(r * 256 + c)) * HW;
        for (int i = threadIdx.x; i < HW; i += blockDim.x) s += p[i];
    }
    __shared__ float sm[256];
    sm[threadIdx.x] = s;
    __syncthreads();
    for (int o = 128; o > 0; o >>= 1) {
        if (threadIdx.x < o) sm[threadIdx.x] += sm[threadIdx.x + o];
        __syncthreads();
    }
    if (threadIdx.x == 0) g_fsum[lvl * 256 + c] = sm[0] / (float)HW;
}

// ---------------- fea_z: all levels, grid (8, 4) ----------------
__global__ void fz_all(const float* __restrict__ fcw4, const float* __restrict__ fcb4)
{
    int lvl = blockIdx.y;
    const float* fcw = fcw4 + lvl * 32768;
    const float* fcb = fcb4 + lvl * 128;
    int g = threadIdx.x >> 4;
    int lane = threadIdx.x & 15;
    int d = blockIdx.x * 16 + g;
    float s = 0.f;
    for (int c = lane; c < 256; c += 16) s += fcw[d * 256 + c] * g_fsum[lvl * 256 + c];
#pragma unroll
    for (int o = 8; o > 0; o >>= 1) s += __shfl_down_sync(0xffffffffu, s, o, 16);
    if (lane == 0) g_fz[lvl * 128 + d] = s + fcb[d];
}

// ---------------- att: all levels, grid (32, 4) ----------------
__global__ void att_all(const float* __restrict__ fcsw4, const float* __restrict__ fcsb4)
{
    int lvl = blockIdx.y;
    const float* fcsw = fcsw4 + lvl * 5 * 256 * 128;
    const float* fcsb = fcsb4 + lvl * 5 * 256;
    __shared__ float fz[128];
    if (threadIdx.x < 128) fz[threadIdx.x] = g_fz[lvl * 128 + threadIdx.x];
    __syncthreads();
    int cl = threadIdx.x >> 5;
    int lane = threadIdx.x & 31;
    int c = blockIdx.x * 8 + cl;
    float lg[5];
#pragma unroll
    for (int m = 0; m < 5; m++) {
        float s = 0.f;
#pragma unroll
        for (int i = 0; i < 4; i++) {
            int d = lane + i * 32;
            s += fz[d] * fcsw[((m * 256 + c) * 128) + d];
        }
#pragma unroll
        for (int o = 16; o > 0; o >>= 1) s += __shfl_down_sync(0xffffffffu, s, o);
        lg[m] = s;
    }
    if (lane == 0) {
        float mx = -1e30f;
#pragma unroll
        for (int m = 0; m < 5; m++) {
            lg[m] += fcsb[m * 256 + c];
            mx = fmaxf(mx, lg[m]);
        }
        float den = 0.f;
#pragma unroll
        for (int m = 0; m < 5; m++) { lg[m] = expf(lg[m] - mx); den += lg[m]; }
        float inv = 1.f / den;
#pragma unroll
        for (int m = 0; m < 5; m++) g_att[lvl * 1280 + m * 256 + c] = lg[m] * inv;
    }
}

// ---------------- out: all levels, flattened ----------------
__global__ void wsum_all(float* __restrict__ out)
{
    constexpr int FEOFF[4]  = {0, 20971520, 26214400, 27525120};
    constexpr int LATOFF[4] = {0, 4194304, 5242880, 5505024};
    constexpr int HWs[4]    = {16384, 4096, 1024, 256};
    constexpr int BSTART[5] = {0, 4096, 5120, 5376, 5440};
    int b = blockIdx.x;
    int lvl = 0;
    if (b >= BSTART[1]) lvl = (b >= BSTART[3]) ? 3 : ((b >= BSTART[2]) ? 2 : 1);
    int i4 = (b - BSTART[lvl]) * 256 + threadIdx.x;
    int HW = HWs[lvl];
    int hw4 = HW >> 2;
    int c = i4 / hw4;
    int p = i4 - c * hw4;
    const float4* f = (const float4*)(g_feas + FEOFF[lvl]);
    const float* att = g_att + lvl * 1280;
    float4 acc = make_float4(0.f, 0.f, 0.f, 0.f);
#pragma unroll
    for (int m = 0; m < 5; m++) {
        float a = att[m * 256 + c];
        float4 v = f[((size_t)(m * 256 + c)) * hw4 + p];
        acc.x = fmaf(a, v.x, acc.x);
        acc.y = fmaf(a, v.y, acc.y);
        acc.z = fmaf(a, v.z, acc.z);
        acc.w = fmaf(a, v.w, acc.w);
    }
    ((float4*)(out + LATOFF[lvl]))[i4] = acc;
}

// ---------------- launch ----------------
extern "C" void kernel_launch(void* const* d_in, const int* in_sizes, int n_in,
                              void* d_out, int out_size)
{
    const float *x[4], *lw[4];
    if (in_sizes[1] == 65536) {           // interleaved: x0,lw0,x1,lw1,...
        for (int i = 0; i < 4; i++) {
            x[i]  = (const float*)d_in[2 * i];
            lw[i] = (const float*)d_in[2 * i + 1];
        }
    } else {                              // grouped: x0..x3, lw0..lw3
        for (int i = 0; i < 4; i++) {
            x[i]  = (const float*)d_in[i];
            lw[i] = (const float*)d_in[4 + i];
        }
    }
    const float* lb   = (const float*)d_in[8];
    const float* aacw = (const float*)d_in[9];
    const float* aacb = (const float*)d_in[10];
    const float* bng  = (const float*)d_in[11];
    const float* bnb  = (const float*)d_in[12];
    const float* bnm  = (const float*)d_in[13];
    const float* bnv  = (const float*)d_in[14];
    const float* fcw  = (const float*)d_in[15];
    const float* fcb  = (const float*)d_in[16];
    const float* fcsw = (const float*)d_in[17];
    const float* fcsb = (const float*)d_in[18];
    float* out = (float*)d_out;

    static const int Hs[4]      = {128, 64, 32, 16};
    static const int cins[4]    = {256, 512, 1024, 2048};
    static const int S[4]       = {1, 2, 4, 8};
    static const int latOff[4]  = {0, 4194304, 5242880, 5505024};

    // 0) weight transpose to tf32 fragment layout
    wt_transpose<<<9216, 256>>>(aacw);

    // 1) lateral 1x1 convs (split-K for small-N levels)
    float* g_lat_p;
    cudaGetSymbolAddress((void**)&g_lat_p, g_lat);
    float* g_part_p;
    cudaGetSymbolAddress((void**)&g_part_p, g_part);
    for (int i = 0; i < 4; i++) {
        int N = Hs[i] * Hs[i];
        int s = S[i];
        dim3 g(N / 64, 4, s);
        float* outp = (s == 1) ? (g_lat_p + latOff[i]) : g_part_p;
        lateral_gemm<<<g, 256>>>(lw[i], x[i], lb + i * 256, outp,
                                 cins[i], cins[i] / s, N, s == 1 ? 1 : 0);
        if (s > 1)
            reduce_part<<<(256 * N + 255) / 256, 256>>>(latOff[i], lb + i * 256, N, s);
    }
    // 2) top-down pathway
    for (int i = 3; i >= 1; i--) {
        int Hd = Hs[i - 1];
        int n4 = 256 * Hd * Hd / 4;
        up_add<<<(n4 + 255) / 256, 256>>>(latOff[i - 1], latOff[i], Hd, Hd);
    }
    // 2b) round lat to tf32 (RN)
    round_lat<<<5440, 256>>>();

    // 3) AAC conv, all levels fused (mma.sync tf32, cp.async double-buffer)
    conv_aac_all<<<dim3(170, 10), 256>>>(aacb, bng, bnb, bnm, bnv);

    // 4) SK fusion tail, all levels fused
    reduce_fsum_all<<<dim3(256, 4), 256>>>();
    fz_all<<<dim3(8, 4), 256>>>(fcw, fcb);
    att_all<<<dim3(32, 4), 256>>>(fcsw, fcsb);
    wsum_all<<<5440, 256>>>(out);

    (void)n_in; (void)out_size;
}

// round 7
// speedup vs baseline: 4.9148x; 1.5030x over previous
#include <cuda_runtime.h>
#include <cuda_fp16.h>
#include <cstdint>
#include <math.h>

// ---------------- scratch (device globals; no allocation) ----------------
__device__ float g_lat[5570560];        // 4 levels of (256,H,W) fp32
__device__ uint32_t g_lath[2785280];    // packed half2 (ic-pair, HW)
__device__ uint32_t g_wt[1179648];      // fp16 weights, mma-fragment order
__device__ float g_feas[27852800];      // 4 levels of (5,256,H,W)
__device__ float g_part[2097152];       // split-K partials
__device__ float g_fsum[4 * 256];
__device__ float g_fz[4 * 128];
__device__ float g_att[4 * 5 * 256];

#define BN_EPS 1e-5f

__device__ __forceinline__ uint32_t smem_u32(const void* p) {
    uint32_t a;
    asm("{ .reg .u64 t; cvta.to.shared.u64 t, %1; cvt.u32.u64 %0, t; }" : "=r"(a) : "l"(p));
    return a;
}
#define CP_ASYNC4(dst, src, sz) \
    asm volatile("cp.async.ca.shared.global [%0], [%1], 4, %2;" \
                 :: "r"(dst), "l"(src), "r"(sz) : "memory")
#define CP_COMMIT() asm volatile("cp.async.commit_group;" ::: "memory")
#define CP_WAIT0()  asm volatile("cp.async.wait_group 0;" ::: "memory")

__device__ __forceinline__ void mma16h(float* c, const uint32_t* a,
                                       uint32_t b0, uint32_t b1) {
    asm volatile(
        "mma.sync.aligned.m16n8k16.row.col.f32.f16.f16.f32 "
        "{%0,%1,%2,%3}, {%4,%5,%6,%7}, {%8,%9}, {%0,%1,%2,%3};"
        : "+f"(c[0]), "+f"(c[1]), "+f"(c[2]), "+f"(c[3])
        : "r"(a[0]), "r"(a[1]), "r"(a[2]), "r"(a[3]), "r"(b0), "r"(b1));
}

// ---------------- weight transpose to fp16 fragment order ----------------
// idx -> q(4 regs), lane(32), t(16 m16-tiles), kc(16 k16-chunks), (lvl,j)
//   oc   = t*16 + (lane>>2) + 8*(q&1)
//   pair = kc*8 + (lane&3) + 4*(q>>1)   (ic pair: 2*pair, 2*pair+1)
__global__ void wt_transpose(const float* __restrict__ aacw)
{
    int idx = blockIdx.x * 256 + threadIdx.x;
    if (idx >= 1179648) return;
    int q = idx & 3;
    int l = (idx >> 2) & 31;
    int t = (idx >> 7) & 15;
    int kc = (idx >> 11) & 15;
    int lj = idx >> 15;           // lvl*9 + j
    int j = lj % 9, lvl = lj / 9;
    int oc = t * 16 + (l >> 2) + 8 * (q & 1);
    int pair = kc * 8 + (l & 3) + 4 * (q >> 1);
    float w0 = aacw[((lvl * 256 + oc) * 256 + 2 * pair) * 9 + j];
    float w1 = aacw[((lvl * 256 + oc) * 256 + 2 * pair + 1) * 9 + j];
    uint32_t h0 = __half_as_ushort(__float2half_rn(w0));
    uint32_t h1 = __half_as_ushort(__float2half_rn(w1));
    g_wt[idx] = (h1 << 16) | h0;
}

// ---------------- convert lat fp32 -> packed half2 (ic-pair major) -------
__global__ void cvt_lat()
{
    constexpr int LATOFF[4]  = {0, 4194304, 5242880, 5505024};
    int idx = blockIdx.x * 256 + threadIdx.x;
    if (idx >= 2785280) return;
    int lvl, off, lhw;
    if (idx < 2097152)      { lvl = 0; off = 0;       lhw = 14; }
    else if (idx < 2621440) { lvl = 1; off = 2097152; lhw = 12; }
    else if (idx < 2752512) { lvl = 2; off = 2621440; lhw = 10; }
    else                    { lvl = 3; off = 2752512; lhw = 8;  }
    int local = idx - off;
    int HW = 1 << lhw;
    int c = local >> lhw;
    int i = local & (HW - 1);
    const float* latp = g_lat + LATOFF[lvl];
    float v0 = latp[(size_t)(2 * c) * HW + i];
    float v1 = latp[(size_t)(2 * c + 1) * HW + i];
    uint32_t h0 = __half_as_ushort(__float2half_rn(v0));
    uint32_t h1 = __half_as_ushort(__float2half_rn(v1));
    g_lath[idx] = (h1 << 16) | h0;
}

// ---------------- lateral 1x1 conv as tiled SGEMM (split-K capable) -------
__global__ __launch_bounds__(256)
void lateral_gemm(const float* __restrict__ A, const float* __restrict__ X,
                  const float* __restrict__ bias, float* __restrict__ outp,
                  int K, int kLen, int N, int addbias)
{
    __shared__ float As[16][64];
    __shared__ float Bs[16][64];
    const int tx = threadIdx.x & 15;
    const int ty = threadIdx.x >> 4;
    const int row0 = blockIdx.y * 64;
    const int col0 = blockIdx.x * 64;
    const int kb = blockIdx.z * kLen;

    float acc[4][4];
#pragma unroll
    for (int i = 0; i < 4; i++)
#pragma unroll
        for (int j = 0; j < 4; j++) acc[i][j] = 0.f;

    for (int k0 = kb; k0 < kb + kLen; k0 += 16) {
#pragma unroll
        for (int i = 0; i < 4; i++) {
            int idx = threadIdx.x + i * 256;
            int r = idx >> 4, k = idx & 15;
            As[k][r] = A[(row0 + r) * K + k0 + k];
        }
#pragma unroll
        for (int i = 0; i < 4; i++) {
            int idx = threadIdx.x + i * 256;
            int k = idx >> 6, c = idx & 63;
            Bs[k][c] = X[(k0 + k) * N + col0 + c];
        }
        __syncthreads();
#pragma unroll
        for (int k = 0; k < 16; k++) {
            float4 a4 = *(const float4*)&As[k][ty * 4];
            float4 b4 = *(const float4*)&Bs[k][tx * 4];
            float a[4] = {a4.x, a4.y, a4.z, a4.w};
            float b[4] = {b4.x, b4.y, b4.z, b4.w};
#pragma unroll
            for (int i = 0; i < 4; i++)
#pragma unroll
                for (int j = 0; j < 4; j++) acc[i][j] = fmaf(a[i], b[j], acc[i][j]);
        }
        __syncthreads();
    }
    float* out = outp + (size_t)blockIdx.z * 256 * N;
#pragma unroll
    for (int i = 0; i < 4; i++) {
        float bv = addbias ? bias[row0 + ty * 4 + i] : 0.f;
#pragma unroll
        for (int j = 0; j < 4; j++)
            out[(row0 + ty * 4 + i) * N + col0 + tx * 4 + j] = acc[i][j] + bv;
    }
}

// reduce split-K partials + bias -> g_lat
__global__ void reduce_part(int latoff, const float* __restrict__ lb, int N, int S)
{
    int idx = blockIdx.x * 256 + threadIdx.x;
    if (idx >= 256 * N) return;
    float s = lb[idx / N];
    for (int z = 0; z < S; z++) s += g_part[(size_t)z * 256 * N + idx];
    g_lat[latoff + idx] = s;
}

// ---------------- nearest 2x upsample-add (dst += up2(src)) ----------------
__global__ void up_add(int dstoff, int srcoff, int H, int W)
{
    int i4 = blockIdx.x * blockDim.x + threadIdx.x;
    int HW = H * W;
    int n4 = (256 * HW) >> 2;
    if (i4 >= n4) return;
    int hw4 = HW >> 2;
    int c = i4 / hw4;
    int rem = i4 - c * hw4;
    int w4 = W >> 2;
    int y = rem / w4;
    int x4 = rem - y * w4;
    int H2 = H >> 1, W2 = W >> 1;
    int selem = c * H2 * W2 + (y >> 1) * W2 + (x4 << 1);
    float2 sv = *(const float2*)(g_lat + srcoff + selem);
    float4* d = (float4*)(g_lat + dstoff) + i4;
    float4 dv = *d;
    dv.x += sv.x; dv.y += sv.x; dv.z += sv.y; dv.w += sv.y;
    *d = dv;
}

// ---------------- AAC conv via mma.sync fp16 k16, ALL LEVELS, 2-buf ------
// grid: (170, 10). blockIdx.x -> (level, 16x8 pixel tile); mb -> (branch, oc half)
__global__ __launch_bounds__(256, 2)
void conv_aac_all(const float* __restrict__ bias4,
                  const float* __restrict__ bng4, const float* __restrict__ bnb4,
                  const float* __restrict__ bnm4, const float* __restrict__ bnv4)
{
    constexpr int ROT[5][9] = {
        {0, 1, 2, 3, 4, 5, 6, 7, 8},
        {3, 0, 1, 6, 4, 2, 7, 8, 5},
        {6, 3, 0, 7, 4, 1, 8, 5, 2},
        {7, 6, 3, 8, 4, 0, 5, 2, 1},
        {8, 7, 6, 5, 4, 3, 2, 1, 0}};
    constexpr int HS[4]      = {128, 64, 32, 16};
    constexpr int LATHOFF[4] = {0, 2097152, 2621440, 2752512};
    constexpr int FEOFF[4]   = {0, 20971520, 26214400, 27525120};
    constexpr int TSTART[5]  = {0, 128, 160, 168, 170};

    __shared__ uint32_t s_in[2][16 * 184];   // double-buffered half2 halo tiles

    const int tid = threadIdx.x;
    const int wid = tid >> 5, lid = tid & 31;
    const int g = lid >> 2, tig = lid & 3;
    const int warp_m = wid & 3, warp_n = wid >> 2;

    int pbx = blockIdx.x;
    int lvl = 0;
    if (pbx >= TSTART[1]) lvl = (pbx >= TSTART[3]) ? 3 : ((pbx >= TSTART[2]) ? 2 : 1);
    const int tb = pbx - TSTART[lvl];
    const int H = HS[lvl], W = H;
    const int HW = H * W;
    const int tiles_x = W >> 4;
    const int tx0 = (tb % tiles_x) << 4;
    const int ty0 = (tb / tiles_x) << 3;
    const int mb = blockIdx.y;
    const int r = mb >> 1;
    const int oc0 = (mb & 1) << 7;

    const float* bias = bias4 + lvl * 256;
    const float* bng = bng4 + lvl * 1280;
    const float* bnb = bnb4 + lvl * 1280;
    const float* bnm = bnm4 + lvl * 1280;
    const float* bnv = bnv4 + lvl * 1280;
    const uint32_t* lath = g_lath + LATHOFF[lvl];
    const uint4* wt4 = (const uint4*)g_wt + lvl * 73728;
    const uint32_t sbase = smem_u32(&s_in[0][0]);

    float c[2][8][4];
#pragma unroll
    for (int mt = 0; mt < 2; mt++)
#pragma unroll
        for (int nt = 0; nt < 8; nt++)
#pragma unroll
            for (int q = 0; q < 4; q++) c[mt][nt][q] = 0.f;

    // ---- async fill of haloed tile [16 icpair][10][18] half2 into buffer b
    auto fill = [&](int icb, int b) {
#pragma unroll 1
        for (int e = tid; e < 2880; e += 256) {
            int icp = e / 180;
            int sp = e - icp * 180;
            int yy = sp / 18, xx = sp - yy * 18;
            int gy = ty0 + yy - 1, gx = tx0 + xx - 1;
            bool ok = ((unsigned)gy < (unsigned)H) && ((unsigned)gx < (unsigned)W);
            const uint32_t* src = lath + ((size_t)(icb * 16 + icp) * HW +
                                          (ok ? (gy * W + gx) : 0));
            uint32_t dst = sbase + (uint32_t)(b * 2944 + icp * 184 + yy * 18 + xx) * 4u;
            CP_ASYNC4(dst, src, ok ? 4u : 0u);
        }
    };

    fill(0, 0);
    CP_COMMIT();
    CP_WAIT0();
    __syncthreads();

    for (int icb = 0; icb < 8; icb++) {
        const int cur = icb & 1;
        if (icb < 7) {
            fill(icb + 1, cur ^ 1);
            CP_COMMIT();
        }
        const uint32_t* sin = &s_in[cur][0];
        for (int j = 0; j < 9; j++) {
            const int jr = ROT[r][j];
            const int dy = j / 3, dx = j % 3;
#pragma unroll
            for (int ks = 0; ks < 2; ks++) {
                const int kc = icb * 2 + ks;   // k16 chunk index (0..15)
                uint32_t a[2][4];
#pragma unroll
                for (int mt = 0; mt < 2; mt++) {
                    int t = (mb & 1) * 8 + warp_m * 2 + mt;
                    uint4 av = wt4[((jr * 16 + kc) * 16 + t) * 32 + lid];
                    a[mt][0] = av.x; a[mt][1] = av.y;
                    a[mt][2] = av.z; a[mt][3] = av.w;
                }
                const int base_lo = (ks * 8 + tig) * 184;
                const int base_hi = base_lo + 4 * 184;
#pragma unroll
                for (int nt = 0; nt < 8; nt++) {
                    int n = warp_n * 64 + nt * 8 + g;
                    int yl = n >> 4, xl = n & 15;
                    int off = (yl + dy) * 18 + xl + dx;
                    uint32_t b0 = sin[base_lo + off];
                    uint32_t b1 = sin[base_hi + off];
                    mma16h(c[0][nt], a[0], b0, b1);
                    mma16h(c[1][nt], a[1], b0, b1);
                }
            }
        }
        if (icb < 7) CP_WAIT0();
        __syncthreads();
    }

    // ---- epilogue: bias + BN + relu -> feas ----
    float* fp = g_feas + FEOFF[lvl] + (size_t)(r * 256 + oc0) * HW + ty0 * W + tx0;
#pragma unroll
    for (int mt = 0; mt < 2; mt++) {
        int m_lo = warp_m * 32 + mt * 16 + g;
        int m_hi = m_lo + 8;
        int oc_lo = oc0 + m_lo, oc_hi = oc0 + m_hi;
        float sc_lo = bng[r * 256 + oc_lo] * rsqrtf(bnv[r * 256 + oc_lo] + BN_EPS);
        float sh_lo = bnb[r * 256 + oc_lo] + (bias[oc_lo] - bnm[r * 256 + oc_lo]) * sc_lo;
        float sc_hi = bng[r * 256 + oc_hi] * rsqrtf(bnv[r * 256 + oc_hi] + BN_EPS);
        float sh_hi = bnb[r * 256 + oc_hi] + (bias[oc_hi] - bnm[r * 256 + oc_hi]) * sc_hi;
#pragma unroll
        for (int nt = 0; nt < 8; nt++) {
            int col = warp_n * 64 + nt * 8 + 2 * tig;
            int yl = col >> 4, xl = col & 15;
            float2 vlo, vhi;
            vlo.x = fmaxf(fmaf(c[mt][nt][0], sc_lo, sh_lo), 0.f);
            vlo.y = fmaxf(fmaf(c[mt][nt][1], sc_lo, sh_lo), 0.f);
            vhi.x = fmaxf(fmaf(c[mt][nt][2], sc_hi, sh_hi), 0.f);
            vhi.y = fmaxf(fmaf(c[mt][nt][3], sc_hi, sh_hi), 0.f);
            *(float2*)(fp + (size_t)m_lo * HW + yl * W + xl) = vlo;
            *(float2*)(fp + (size_t)m_hi * HW + yl * W + xl) = vhi;
        }
    }
}

// ---------------- fea_s: all levels, grid (256, 4) ----------------
__global__ void reduce_fsum_all()
{
    constexpr int FEOFF[4] = {0, 20971520, 26214400, 27525120};
    constexpr int HWs[4]   = {16384, 4096, 1024, 256};
    int lvl = blockIdx.y;
    int HW = HWs[lvl];
    int c = blockIdx.x;
    const float* f = g_feas + FEOFF[lvl];
    float s = 0.f;
    for (int r = 0; r < 5; r++) {
        const float* p = f + ((size_t)(r * 256 + c)) * HW;
        for (int i = threadIdx.x; i < HW; i += blockDim.x) s += p[i];
    }
    __shared__ float sm[256];
    sm[threadIdx.x] = s;
    __syncthreads();
    for (int o = 128; o > 0; o >>= 1) {
        if (threadIdx.x < o) sm[threadIdx.x] += sm[threadIdx.x + o];
        __syncthreads();
    }
    if (threadIdx.x == 0) g_fsum[lvl * 256 + c] = sm[0] / (float)HW;
}

// ---------------- fea_z: all levels, grid (8, 4) ----------------
__global__ void fz_all(const float* __restrict__ fcw4, const float* __restrict__ fcb4)
{
    int lvl = blockIdx.y;
    const float* fcw = fcw4 + lvl * 32768;
    const float* fcb = fcb4 + lvl * 128;
    int g = threadIdx.x >> 4;
    int lane = threadIdx.x & 15;
    int d = blockIdx.x * 16 + g;
    float s = 0.f;
    for (int c = lane; c < 256; c += 16) s += fcw[d * 256 + c] * g_fsum[lvl * 256 + c];
#pragma unroll
    for (int o = 8; o > 0; o >>= 1) s += __shfl_down_sync(0xffffffffu, s, o, 16);
    if (lane == 0) g_fz[lvl * 128 + d] = s + fcb[d];
}

// ---------------- att: all levels, grid (32, 4) ----------------
__global__ void att_all(const float* __restrict__ fcsw4, const float* __restrict__ fcsb4)
{
    int lvl = blockIdx.y;
    const float* fcsw = fcsw4 + lvl * 5 * 256 * 128;
    const float* fcsb = fcsb4 + lvl * 5 * 256;
    __shared__ float fz[128];
    if (threadIdx.x < 128) fz[threadIdx.x] = g_fz[lvl * 128 + threadIdx.x];
    __syncthreads();
    int cl = threadIdx.x >> 5;
    int lane = threadIdx.x & 31;
    int c = blockIdx.x * 8 + cl;
    float lg[5];
#pragma unroll
    for (int m = 0; m < 5; m++) {
        float s = 0.f;
#pragma unroll
        for (int i = 0; i < 4; i++) {
            int d = lane + i * 32;
            s += fz[d] * fcsw[((m * 256 + c) * 128) + d];
        }
#pragma unroll
        for (int o = 16; o > 0; o >>= 1) s += __shfl_down_sync(0xffffffffu, s, o);
        lg[m] = s;
    }
    if (lane == 0) {
        float mx = -1e30f;
#pragma unroll
        for (int m = 0; m < 5; m++) {
            lg[m] += fcsb[m * 256 + c];
            mx = fmaxf(mx, lg[m]);
        }
        float den = 0.f;
#pragma unroll
        for (int m = 0; m < 5; m++) { lg[m] = expf(lg[m] - mx); den += lg[m]; }
        float inv = 1.f / den;
#pragma unroll
        for (int m = 0; m < 5; m++) g_att[lvl * 1280 + m * 256 + c] = lg[m] * inv;
    }
}

// ---------------- out: all levels, flattened ----------------
__global__ void wsum_all(float* __restrict__ out)
{
    constexpr int FEOFF[4]  = {0, 20971520, 26214400, 27525120};
    constexpr int LATOFF[4] = {0, 4194304, 5242880, 5505024};
    constexpr int HWs[4]    = {16384, 4096, 1024, 256};
    constexpr int BSTART[5] = {0, 4096, 5120, 5376, 5440};
    int b = blockIdx.x;
    int lvl = 0;
    if (b >= BSTART[1]) lvl = (b >= BSTART[3]) ? 3 : ((b >= BSTART[2]) ? 2 : 1);
    int i4 = (b - BSTART[lvl]) * 256 + threadIdx.x;
    int HW = HWs[lvl];
    int hw4 = HW >> 2;
    int c = i4 / hw4;
    int p = i4 - c * hw4;
    const float4* f = (const float4*)(g_feas + FEOFF[lvl]);
    const float* att = g_att + lvl * 1280;
    float4 acc = make_float4(0.f, 0.f, 0.f, 0.f);
#pragma unroll
    for (int m = 0; m < 5; m++) {
        float a = att[m * 256 + c];
        float4 v = f[((size_t)(m * 256 + c)) * hw4 + p];
        acc.x = fmaf(a, v.x, acc.x);
        acc.y = fmaf(a, v.y, acc.y);
        acc.z = fmaf(a, v.z, acc.z);
        acc.w = fmaf(a, v.w, acc.w);
    }
    ((float4*)(out + LATOFF[lvl]))[i4] = acc;
}

// ---------------- launch ----------------
extern "C" void kernel_launch(void* const* d_in, const int* in_sizes, int n_in,
                              void* d_out, int out_size)
{
    const float *x[4], *lw[4];
    if (in_sizes[1] == 65536) {           // interleaved: x0,lw0,x1,lw1,...
        for (int i = 0; i < 4; i++) {
            x[i]  = (const float*)d_in[2 * i];
            lw[i] = (const float*)d_in[2 * i + 1];
        }
    } else {                              // grouped: x0..x3, lw0..lw3
        for (int i = 0; i < 4; i++) {
            x[i]  = (const float*)d_in[i];
            lw[i] = (const float*)d_in[4 + i];
        }
    }
    const float* lb   = (const float*)d_in[8];
    const float* aacw = (const float*)d_in[9];
    const float* aacb = (const float*)d_in[10];
    const float* bng  = (const float*)d_in[11];
    const float* bnb  = (const float*)d_in[12];
    const float* bnm  = (const float*)d_in[13];
    const float* bnv  = (const float*)d_in[14];
    const float* fcw  = (const float*)d_in[15];
    const float* fcb  = (const float*)d_in[16];
    const float* fcsw = (const float*)d_in[17];
    const float* fcsb = (const float*)d_in[18];
    float* out = (float*)d_out;

    static const int Hs[4]      = {128, 64, 32, 16};
    static const int cins[4]    = {256, 512, 1024, 2048};
    static const int S[4]       = {1, 2, 4, 8};
    static const int latOff[4]  = {0, 4194304, 5242880, 5505024};

    // 0) weight transpose to fp16 fragment layout
    wt_transpose<<<4608, 256>>>(aacw);

    // 1) lateral 1x1 convs (split-K for small-N levels)
    float* g_lat_p;
    cudaGetSymbolAddress((void**)&g_lat_p, g_lat);
    float* g_part_p;
    cudaGetSymbolAddress((void**)&g_part_p, g_part);
    for (int i = 0; i < 4; i++) {
        int N = Hs[i] * Hs[i];
        int s = S[i];
        dim3 g(N / 64, 4, s);
        float* outp = (s == 1) ? (g_lat_p + latOff[i]) : g_part_p;
        lateral_gemm<<<g, 256>>>(lw[i], x[i], lb + i * 256, outp,
                                 cins[i], cins[i] / s, N, s == 1 ? 1 : 0);
        if (s > 1)
            reduce_part<<<(256 * N + 255) / 256, 256>>>(latOff[i], lb + i * 256, N, s);
    }
    // 2) top-down pathway
    for (int i = 3; i >= 1; i--) {
        int Hd = Hs[i - 1];
        int n4 = 256 * Hd * Hd / 4;
        up_add<<<(n4 + 255) / 256, 256>>>(latOff[i - 1], latOff[i], Hd, Hd);
    }
    // 2b) convert lat to packed half2
    cvt_lat<<<10880, 256>>>();

    // 3) AAC conv, all levels fused (mma.sync fp16 k16, cp.async 2-buffer)
    conv_aac_all<<<dim3(170, 10), 256>>>(aacb, bng, bnb, bnm, bnv);

    // 4) SK fusion tail, all levels fused
    reduce_fsum_all<<<dim3(256, 4), 256>>>();
    fz_all<<<dim3(8, 4), 256>>>(fcw, fcb);
    att_all<<<dim3(32, 4), 256>>>(fcsw, fcsb);
    wsum_all<<<5440, 256>>>(out);

    (void)n_in; (void)out_size;
}

// round 8
// speedup vs baseline: 6.3535x; 1.2927x over previous
#include <cuda_runtime.h>
#include <cuda_fp16.h>
#include <cstdint>
#include <math.h>

// ---------------- scratch (device globals; no allocation) ----------------
__device__ float g_lat[5570560];        // 4 levels of (256,H,W) fp32
__device__ uint32_t g_lath[2785280];    // packed half2 (ic-pair, HW)
__device__ uint32_t g_wt[1179648];      // fp16 conv weights, fragment order
__device__ uint32_t g_lwh[491520];      // fp16 lateral weights, fragment order
__device__ uint32_t g_xh[3932160];      // packed half2 x inputs (k-pair, HW)
__device__ uint32_t g_feash[13926400];  // feas as half2 (px pairs)
__device__ float g_part[2097152];       // split-K partials
__device__ float g_fsum[4 * 256];
__device__ float g_fz[4 * 128];
__device__ float g_att[4 * 5 * 256];

#define BN_EPS 1e-5f

__device__ __forceinline__ uint32_t smem_u32(const void* p) {
    uint32_t a;
    asm("{ .reg .u64 t; cvta.to.shared.u64 t, %1; cvt.u32.u64 %0, t; }" : "=r"(a) : "l"(p));
    return a;
}
#define CP_ASYNC4(dst, src, sz) \
    asm volatile("cp.async.ca.shared.global [%0], [%1], 4, %2;" \
                 :: "r"(dst), "l"(src), "r"(sz) : "memory")
#define CP_ASYNC16(dst, src) \
    asm volatile("cp.async.cg.shared.global [%0], [%1], 16;" \
                 :: "r"(dst), "l"(src) : "memory")
#define CP_COMMIT() asm volatile("cp.async.commit_group;" ::: "memory")
#define CP_WAIT0()  asm volatile("cp.async.wait_group 0;" ::: "memory")

__device__ __forceinline__ void mma16h(float* c, const uint32_t* a,
                                       uint32_t b0, uint32_t b1) {
    asm volatile(
        "mma.sync.aligned.m16n8k16.row.col.f32.f16.f16.f32 "
        "{%0,%1,%2,%3}, {%4,%5,%6,%7}, {%8,%9}, {%0,%1,%2,%3};"
        : "+f"(c[0]), "+f"(c[1]), "+f"(c[2]), "+f"(c[3])
        : "r"(a[0]), "r"(a[1]), "r"(a[2]), "r"(a[3]), "r"(b0), "r"(b1));
}
__device__ __forceinline__ uint32_t packh2(float a, float b) {
    uint32_t h0 = __half_as_ushort(__float2half_rn(a));
    uint32_t h1 = __half_as_ushort(__float2half_rn(b));
    return (h1 << 16) | h0;
}

// ---------------- conv weight transpose to fp16 fragment order -----------
__global__ void wt_transpose(const float* __restrict__ aacw)
{
    int idx = blockIdx.x * 256 + threadIdx.x;
    if (idx >= 1179648) return;
    int q = idx & 3;
    int l = (idx >> 2) & 31;
    int t = (idx >> 7) & 15;
    int kc = (idx >> 11) & 15;
    int lj = idx >> 15;           // lvl*9 + j
    int j = lj % 9, lvl = lj / 9;
    int oc = t * 16 + (l >> 2) + 8 * (q & 1);
    int pair = kc * 8 + (l & 3) + 4 * (q >> 1);
    float w0 = aacw[((lvl * 256 + oc) * 256 + 2 * pair) * 9 + j];
    float w1 = aacw[((lvl * 256 + oc) * 256 + 2 * pair + 1) * 9 + j];
    g_wt[idx] = packh2(w0, w1);
}

// ---------------- lateral weight transpose (per level) --------------------
__global__ void wt_lat(const float* __restrict__ lw, int K, int dstoff)
{
    int idx = blockIdx.x * 256 + threadIdx.x;
    if (idx >= 128 * K) return;   // 256*K/2
    int q = idx & 3;
    int l = (idx >> 2) & 31;
    int t = (idx >> 7) & 15;
    int kc = idx >> 11;
    int oc = t * 16 + (l >> 2) + 8 * (q & 1);
    int pair = kc * 8 + (l & 3) + 4 * (q >> 1);
    g_lwh[dstoff + idx] = packh2(lw[oc * K + 2 * pair], lw[oc * K + 2 * pair + 1]);
}

// ---------------- x -> packed half2 (per level) ---------------------------
__global__ void cvt_x(const float* __restrict__ x, int K2, int N, int dstoff)
{
    int idx = blockIdx.x * 256 + threadIdx.x;
    if (idx >= K2 * N) return;
    int p = idx / N;
    int n = idx - p * N;
    g_xh[dstoff + idx] = packh2(x[(size_t)(2 * p) * N + n],
                                x[(size_t)(2 * p + 1) * N + n]);
}

// ---------------- convert lat fp32 -> packed half2 (ic-pair major) -------
__global__ void cvt_lat()
{
    constexpr int LATOFF[4]  = {0, 4194304, 5242880, 5505024};
    int idx = blockIdx.x * 256 + threadIdx.x;
    if (idx >= 2785280) return;
    int lvl, off, lhw;
    if (idx < 2097152)      { lvl = 0; off = 0;       lhw = 14; }
    else if (idx < 2621440) { lvl = 1; off = 2097152; lhw = 12; }
    else if (idx < 2752512) { lvl = 2; off = 2621440; lhw = 10; }
    else                    { lvl = 3; off = 2752512; lhw = 8;  }
    int local = idx - off;
    int HW = 1 << lhw;
    int c = local >> lhw;
    int i = local & (HW - 1);
    const float* latp = g_lat + LATOFF[lvl];
    g_lath[idx] = packh2(latp[(size_t)(2 * c) * HW + i],
                         latp[(size_t)(2 * c + 1) * HW + i]);
}

// ---------------- lateral 1x1 conv via fp16 mma (split-K) ----------------
// grid (N/128, 2, S). C[256,N] = lw[256,K] * xh[K,N]; kLen = K/S (mult of 32)
__global__ __launch_bounds__(256, 2)
void lat_mma(const uint32_t* __restrict__ lwh, const uint32_t* __restrict__ xh,
             const float* __restrict__ bias, float* __restrict__ outp,
             int kLen, int N, int addbias)
{
    __shared__ uint32_t sB[2][16 * 136];
    const int tid = threadIdx.x;
    const int wid = tid >> 5, lid = tid & 31;
    const int g = lid >> 2, tig = lid & 3;
    const int warp_m = wid & 3, warp_n = wid >> 2;
    const int n0 = blockIdx.x * 128;
    const int my = blockIdx.y;
    const int kb = blockIdx.z * kLen;
    const uint32_t sbase = smem_u32(&sB[0][0]);
    const uint4* lw4 = (const uint4*)lwh;

    float c[2][8][4];
#pragma unroll
    for (int mt = 0; mt < 2; mt++)
#pragma unroll
        for (int nt = 0; nt < 8; nt++)
#pragma unroll
            for (int q = 0; q < 4; q++) c[mt][nt][q] = 0.f;

    auto fill = [&](int ch, int b) {
        const int p0 = (kb >> 1) + ch * 16;
#pragma unroll
        for (int e = tid; e < 512; e += 256) {
            int row = e >> 5, cw = e & 31;
            const uint32_t* src = xh + (size_t)(p0 + row) * N + n0 + cw * 4;
            uint32_t dst = sbase + (uint32_t)(b * 2176 + row * 136 + cw * 4) * 4u;
            CP_ASYNC16(dst, src);
        }
    };

    const int nch = kLen >> 5;
    fill(0, 0);
    CP_COMMIT();
    CP_WAIT0();
    __syncthreads();

    for (int ch = 0; ch < nch; ch++) {
        const int cur = ch & 1;
        if (ch + 1 < nch) {
            fill(ch + 1, cur ^ 1);
            CP_COMMIT();
        }
        const uint32_t* s = &sB[cur][0];
#pragma unroll
        for (int ks = 0; ks < 2; ks++) {
            const int kc = (kb >> 4) + ch * 2 + ks;
            uint32_t a[2][4];
#pragma unroll
            for (int mt = 0; mt < 2; mt++) {
                int t = my * 8 + warp_m * 2 + mt;
                uint4 av = lw4[(kc * 16 + t) * 32 + lid];
                a[mt][0] = av.x; a[mt][1] = av.y;
                a[mt][2] = av.z; a[mt][3] = av.w;
            }
            const int base_lo = (ks * 8 + tig) * 136;
            const int base_hi = base_lo + 4 * 136;
#pragma unroll
            for (int nt = 0; nt < 8; nt++) {
                int n = warp_n * 64 + nt * 8 + g;
                mma16h(c[0][nt], a[0], s[base_lo + n], s[base_hi + n]);
                mma16h(c[1][nt], a[1], s[base_lo + n], s[base_hi + n]);
            }
        }
        if (ch + 1 < nch) CP_WAIT0();
        __syncthreads();
    }

    float* out = outp + (size_t)blockIdx.z * 256 * N;
#pragma unroll
    for (int mt = 0; mt < 2; mt++) {
        int oc_lo = (my * 8 + warp_m * 2 + mt) * 16 + g;
        int oc_hi = oc_lo + 8;
        float blo = addbias ? bias[oc_lo] : 0.f;
        float bhi = addbias ? bias[oc_hi] : 0.f;
#pragma unroll
        for (int nt = 0; nt < 8; nt++) {
            int col = n0 + warp_n * 64 + nt * 8 + 2 * tig;
            *(float2*)(out + (size_t)oc_lo * N + col) =
                make_float2(c[mt][nt][0] + blo, c[mt][nt][1] + blo);
            *(float2*)(out + (size_t)oc_hi * N + col) =
                make_float2(c[mt][nt][2] + bhi, c[mt][nt][3] + bhi);
        }
    }
}

// reduce split-K partials + bias -> g_lat
__global__ void reduce_part(int latoff, const float* __restrict__ lb, int N, int S)
{
    int idx = blockIdx.x * 256 + threadIdx.x;
    if (idx >= 256 * N) return;
    float s = lb[idx / N];
    for (int z = 0; z < S; z++) s += g_part[(size_t)z * 256 * N + idx];
    g_lat[latoff + idx] = s;
}

// ---------------- nearest 2x upsample-add (dst += up2(src)) ----------------
__global__ void up_add(int dstoff, int srcoff, int H, int W)
{
    int i4 = blockIdx.x * blockDim.x + threadIdx.x;
    int HW = H * W;
    int n4 = (256 * HW) >> 2;
    if (i4 >= n4) return;
    int hw4 = HW >> 2;
    int c = i4 / hw4;
    int rem = i4 - c * hw4;
    int w4 = W >> 2;
    int y = rem / w4;
    int x4 = rem - y * w4;
    int H2 = H >> 1, W2 = W >> 1;
    int selem = c * H2 * W2 + (y >> 1) * W2 + (x4 << 1);
    float2 sv = *(const float2*)(g_lat + srcoff + selem);
    float4* d = (float4*)(g_lat + dstoff) + i4;
    float4 dv = *d;
    dv.x += sv.x; dv.y += sv.x; dv.z += sv.y; dv.w += sv.y;
    *d = dv;
}

// ---------------- AAC conv via mma.sync fp16 k16, ALL LEVELS, 2-buf ------
__global__ __launch_bounds__(256, 2)
void conv_aac_all(const float* __restrict__ bias4,
                  const float* __restrict__ bng4, const float* __restrict__ bnb4,
                  const float* __restrict__ bnm4, const float* __restrict__ bnv4)
{
    constexpr int ROT[5][9] = {
        {0, 1, 2, 3, 4, 5, 6, 7, 8},
        {3, 0, 1, 6, 4, 2, 7, 8, 5},
        {6, 3, 0, 7, 4, 1, 8, 5, 2},
        {7, 6, 3, 8, 4, 0, 5, 2, 1},
        {8, 7, 6, 5, 4, 3, 2, 1, 0}};
    constexpr int HS[4]      = {128, 64, 32, 16};
    constexpr int LATHOFF[4] = {0, 2097152, 2621440, 2752512};
    constexpr int FEOFFH[4]  = {0, 10485760, 13107200, 13762560};
    constexpr int TSTART[5]  = {0, 128, 160, 168, 170};

    __shared__ uint32_t s_in[2][16 * 184];

    const int tid = threadIdx.x;
    const int wid = tid >> 5, lid = tid & 31;
    const int g = lid >> 2, tig = lid & 3;
    const int warp_m = wid & 3, warp_n = wid >> 2;

    int pbx = blockIdx.x;
    int lvl = 0;
    if (pbx >= TSTART[1]) lvl = (pbx >= TSTART[3]) ? 3 : ((pbx >= TSTART[2]) ? 2 : 1);
    const int tb = pbx - TSTART[lvl];
    const int H = HS[lvl], W = H;
    const int HW = H * W;
    const int tiles_x = W >> 4;
    const int tx0 = (tb % tiles_x) << 4;
    const int ty0 = (tb / tiles_x) << 3;
    const int mb = blockIdx.y;
    const int r = mb >> 1;
    const int oc0 = (mb & 1) << 7;

    const float* bias = bias4 + lvl * 256;
    const float* bng = bng4 + lvl * 1280;
    const float* bnb = bnb4 + lvl * 1280;
    const float* bnm = bnm4 + lvl * 1280;
    const float* bnv = bnv4 + lvl * 1280;
    const uint32_t* lath = g_lath + LATHOFF[lvl];
    const uint4* wt4 = (const uint4*)g_wt + lvl * 73728;
    const uint32_t sbase = smem_u32(&s_in[0][0]);

    float c[2][8][4];
#pragma unroll
    for (int mt = 0; mt < 2; mt++)
#pragma unroll
        for (int nt = 0; nt < 8; nt++)
#pragma unroll
            for (int q = 0; q < 4; q++) c[mt][nt][q] = 0.f;

    auto fill = [&](int icb, int b) {
#pragma unroll 1
        for (int e = tid; e < 2880; e += 256) {
            int icp = e / 180;
            int sp = e - icp * 180;
            int yy = sp / 18, xx = sp - yy * 18;
            int gy = ty0 + yy - 1, gx = tx0 + xx - 1;
            bool ok = ((unsigned)gy < (unsigned)H) && ((unsigned)gx < (unsigned)W);
            const uint32_t* src = lath + ((size_t)(icb * 16 + icp) * HW +
                                          (ok ? (gy * W + gx) : 0));
            uint32_t dst = sbase + (uint32_t)(b * 2944 + icp * 184 + yy * 18 + xx) * 4u;
            CP_ASYNC4(dst, src, ok ? 4u : 0u);
        }
    };

    fill(0, 0);
    CP_COMMIT();
    CP_WAIT0();
    __syncthreads();

    for (int icb = 0; icb < 8; icb++) {
        const int cur = icb & 1;
        if (icb < 7) {
            fill(icb + 1, cur ^ 1);
            CP_COMMIT();
        }
        const uint32_t* sin = &s_in[cur][0];
        for (int j = 0; j < 9; j++) {
            const int jr = ROT[r][j];
            const int dy = j / 3, dx = j % 3;
#pragma unroll
            for (int ks = 0; ks < 2; ks++) {
                const int kc = icb * 2 + ks;
                uint32_t a[2][4];
#pragma unroll
                for (int mt = 0; mt < 2; mt++) {
                    int t = (mb & 1) * 8 + warp_m * 2 + mt;
                    uint4 av = wt4[((jr * 16 + kc) * 16 + t) * 32 + lid];
                    a[mt][0] = av.x; a[mt][1] = av.y;
                    a[mt][2] = av.z; a[mt][3] = av.w;
                }
                const int base_lo = (ks * 8 + tig) * 184;
                const int base_hi = base_lo + 4 * 184;
#pragma unroll
                for (int nt = 0; nt < 8; nt++) {
                    int n = warp_n * 64 + nt * 8 + g;
                    int yl = n >> 4, xl = n & 15;
                    int off = (yl + dy) * 18 + xl + dx;
                    mma16h(c[0][nt], a[0], sin[base_lo + off], sin[base_hi + off]);
                    mma16h(c[1][nt], a[1], sin[base_lo + off], sin[base_hi + off]);
                }
            }
        }
        if (icb < 7) CP_WAIT0();
        __syncthreads();
    }

    // ---- epilogue: bias + BN + relu -> feas (half2 pairs) ----
    uint32_t* fp = g_feash + FEOFFH[lvl] +
                   ((size_t)(r * 256 + oc0) * HW + ty0 * W + tx0) / 2;
#pragma unroll
    for (int mt = 0; mt < 2; mt++) {
        int m_lo = warp_m * 32 + mt * 16 + g;
        int m_hi = m_lo + 8;
        int oc_lo = oc0 + m_lo, oc_hi = oc0 + m_hi;
        float sc_lo = bng[r * 256 + oc_lo] * rsqrtf(bnv[r * 256 + oc_lo] + BN_EPS);
        float sh_lo = bnb[r * 256 + oc_lo] + (bias[oc_lo] - bnm[r * 256 + oc_lo]) * sc_lo;
        float sc_hi = bng[r * 256 + oc_hi] * rsqrtf(bnv[r * 256 + oc_hi] + BN_EPS);
        float sh_hi = bnb[r * 256 + oc_hi] + (bias[oc_hi] - bnm[r * 256 + oc_hi]) * sc_hi;
#pragma unroll
        for (int nt = 0; nt < 8; nt++) {
            int col = warp_n * 64 + nt * 8 + 2 * tig;
            int yl = col >> 4, xl = col & 15;
            float v0 = fmaxf(fmaf(c[mt][nt][0], sc_lo, sh_lo), 0.f);
            float v1 = fmaxf(fmaf(c[mt][nt][1], sc_lo, sh_lo), 0.f);
            float v2 = fmaxf(fmaf(c[mt][nt][2], sc_hi, sh_hi), 0.f);
            float v3 = fmaxf(fmaf(c[mt][nt][3], sc_hi, sh_hi), 0.f);
            fp[((size_t)m_lo * HW + yl * W + xl) / 2] = packh2(v0, v1);
            fp[((size_t)m_hi * HW + yl * W + xl) / 2] = packh2(v2, v3);
        }
    }
}

// ---------------- fea_s: all levels, grid (256, 4) ----------------
__global__ void reduce_fsum_all()
{
    constexpr int FEOFFH[4] = {0, 10485760, 13107200, 13762560};
    constexpr int HWs[4]    = {16384, 4096, 1024, 256};
    int lvl = blockIdx.y;
    int HW2 = HWs[lvl] >> 1;
    int c = blockIdx.x;
    const uint32_t* f = g_feash + FEOFFH[lvl];
    float s = 0.f;
    for (int r = 0; r < 5; r++) {
        const uint32_t* p = f + (size_t)(r * 256 + c) * HW2;
        for (int i = threadIdx.x; i < HW2; i += blockDim.x) {
            float2 v = __half22float2(*(const __half2*)&p[i]);
            s += v.x + v.y;
        }
    }
    __shared__ float sm[256];
    sm[threadIdx.x] = s;
    __syncthreads();
    for (int o = 128; o > 0; o >>= 1) {
        if (threadIdx.x < o) sm[threadIdx.x] += sm[threadIdx.x + o];
        __syncthreads();
    }
    if (threadIdx.x == 0) g_fsum[lvl * 256 + c] = sm[0] / (float)HWs[lvl];
}

// ---------------- fea_z: all levels, grid (8, 4) ----------------
__global__ void fz_all(const float* __restrict__ fcw4, const float* __restrict__ fcb4)
{
    int lvl = blockIdx.y;
    const float* fcw = fcw4 + lvl * 32768;
    const float* fcb = fcb4 + lvl * 128;
    int g = threadIdx.x >> 4;
    int lane = threadIdx.x & 15;
    int d = blockIdx.x * 16 + g;
    float s = 0.f;
    for (int c = lane; c < 256; c += 16) s += fcw[d * 256 + c] * g_fsum[lvl * 256 + c];
#pragma unroll
    for (int o = 8; o > 0; o >>= 1) s += __shfl_down_sync(0xffffffffu, s, o, 16);
    if (lane == 0) g_fz[lvl * 128 + d] = s + fcb[d];
}

// ---------------- att: all levels, grid (32, 4) ----------------
__global__ void att_all(const float* __restrict__ fcsw4, const float* __restrict__ fcsb4)
{
    int lvl = blockIdx.y;
    const float* fcsw = fcsw4 + lvl * 5 * 256 * 128;
    const float* fcsb = fcsb4 + lvl * 5 * 256;
    __shared__ float fz[128];
    if (threadIdx.x < 128) fz[threadIdx.x] = g_fz[lvl * 128 + threadIdx.x];
    __syncthreads();
    int cl = threadIdx.x >> 5;
    int lane = threadIdx.x & 31;
    int c = blockIdx.x * 8 + cl;
    float lg[5];
#pragma unroll
    for (int m = 0; m < 5; m++) {
        float s = 0.f;
#pragma unroll
        for (int i = 0; i < 4; i++) {
            int d = lane + i * 32;
            s += fz[d] * fcsw[((m * 256 + c) * 128) + d];
        }
#pragma unroll
        for (int o = 16; o > 0; o >>= 1) s += __shfl_down_sync(0xffffffffu, s, o);
        lg[m] = s;
    }
    if (lane == 0) {
        float mx = -1e30f;
#pragma unroll
        for (int m = 0; m < 5; m++) {
            lg[m] += fcsb[m * 256 + c];
            mx = fmaxf(mx, lg[m]);
        }
        float den = 0.f;
#pragma unroll
        for (int m = 0; m < 5; m++) { lg[m] = expf(lg[m] - mx); den += lg[m]; }
        float inv = 1.f / den;
#pragma unroll
        for (int m = 0; m < 5; m++) g_att[lvl * 1280 + m * 256 + c] = lg[m] * inv;
    }
}

// ---------------- out: all levels, flattened (4 px / thread) --------------
__global__ void wsum_all(float* __restrict__ out)
{
    constexpr int FEOFFH[4] = {0, 10485760, 13107200, 13762560};
    constexpr int LATOFF[4] = {0, 4194304, 5242880, 5505024};
    constexpr int HWs[4]    = {16384, 4096, 1024, 256};
    constexpr int BSTART[5] = {0, 4096, 5120, 5376, 5440};
    int b = blockIdx.x;
    int lvl = 0;
    if (b >= BSTART[1]) lvl = (b >= BSTART[3]) ? 3 : ((b >= BSTART[2]) ? 2 : 1);
    int i4 = (b - BSTART[lvl]) * 256 + threadIdx.x;
    int HW = HWs[lvl];
    int hw4 = HW >> 2;
    int c = i4 / hw4;
    int p = i4 - c * hw4;
    const uint32_t* f = g_feash + FEOFFH[lvl];
    const float* att = g_att + lvl * 1280;
    float4 acc = make_float4(0.f, 0.f, 0.f, 0.f);
#pragma unroll
    for (int m = 0; m < 5; m++) {
        float a = att[m * 256 + c];
        uint2 raw = *(const uint2*)&f[(size_t)(m * 256 + c) * (HW >> 1) + p * 2];
        float2 v01 = __half22float2(*(const __half2*)&raw.x);
        float2 v23 = __half22float2(*(const __half2*)&raw.y);
        acc.x = fmaf(a, v01.x, acc.x);
        acc.y = fmaf(a, v01.y, acc.y);
        acc.z = fmaf(a, v23.x, acc.z);
        acc.w = fmaf(a, v23.y, acc.w);
    }
    ((float4*)(out + LATOFF[lvl]))[i4] = acc;
}

// ---------------- launch ----------------
extern "C" void kernel_launch(void* const* d_in, const int* in_sizes, int n_in,
                              void* d_out, int out_size)
{
    const float *x[4], *lw[4];
    if (in_sizes[1] == 65536) {           // interleaved: x0,lw0,x1,lw1,...
        for (int i = 0; i < 4; i++) {
            x[i]  = (const float*)d_in[2 * i];
            lw[i] = (const float*)d_in[2 * i + 1];
        }
    } else {                              // grouped: x0..x3, lw0..lw3
        for (int i = 0; i < 4; i++) {
            x[i]  = (const float*)d_in[i];
            lw[i] = (const float*)d_in[4 + i];
        }
    }
    const float* lb   = (const float*)d_in[8];
    const float* aacw = (const float*)d_in[9];
    const float* aacb = (const float*)d_in[10];
    const float* bng  = (const float*)d_in[11];
    const float* bnb  = (const float*)d_in[12];
    const float* bnm  = (const float*)d_in[13];
    const float* bnv  = (const float*)d_in[14];
    const float* fcw  = (const float*)d_in[15];
    const float* fcb  = (const float*)d_in[16];
    const float* fcsw = (const float*)d_in[17];
    const float* fcsb = (const float*)d_in[18];
    float* out = (float*)d_out;

    static const int Hs[4]     = {128, 64, 32, 16};
    static const int cins[4]   = {256, 512, 1024, 2048};
    static const int S[4]      = {1, 2, 4, 8};
    static const int latOff[4] = {0, 4194304, 5242880, 5505024};
    static const int lwOff[4]  = {0, 32768, 98304, 229376};
    static const int xOff[4]   = {0, 2097152, 3145728, 3670016};

    uint32_t *g_lwh_p, *g_xh_p;
    float *g_lat_p, *g_part_p;
    cudaGetSymbolAddress((void**)&g_lat_p, g_lat);
    cudaGetSymbolAddress((void**)&g_part_p, g_part);
    cudaGetSymbolAddress((void**)&g_lwh_p, g_lwh);
    cudaGetSymbolAddress((void**)&g_xh_p, g_xh);

    // 0) weight transposes + x conversion
    wt_transpose<<<4608, 256>>>(aacw);
    for (int i = 0; i < 4; i++) {
        int K = cins[i];
        wt_lat<<<(128 * K + 255) / 256, 256>>>(lw[i], K, lwOff[i]);
        int K2N = (K / 2) * Hs[i] * Hs[i];
        cvt_x<<<(K2N + 255) / 256, 256>>>(x[i], K / 2, Hs[i] * Hs[i], xOff[i]);
    }

    // 1) lateral 1x1 convs on tensor cores (split-K)
    for (int i = 0; i < 4; i++) {
        int N = Hs[i] * Hs[i];
        int s = S[i];
        dim3 g(N / 128, 2, s);
        float* outp = (s == 1) ? (g_lat_p + latOff[i]) : g_part_p;
        lat_mma<<<g, 256>>>(g_lwh_p + lwOff[i], g_xh_p + xOff[i],
                            lb + i * 256, outp, cins[i] / s, N, s == 1 ? 1 : 0);
        if (s > 1)
            reduce_part<<<(256 * N + 255) / 256, 256>>>(latOff[i], lb + i * 256, N, s);
    }
    // 2) top-down pathway
    for (int i = 3; i >= 1; i--) {
        int Hd = Hs[i - 1];
        int n4 = 256 * Hd * Hd / 4;
        up_add<<<(n4 + 255) / 256, 256>>>(latOff[i - 1], latOff[i], Hd, Hd);
    }
    // 2b) convert lat to packed half2
    cvt_lat<<<10880, 256>>>();

    // 3) AAC conv, all levels fused
    conv_aac_all<<<dim3(170, 10), 256>>>(aacb, bng, bnb, bnm, bnv);

    // 4) SK fusion tail, all levels fused
    reduce_fsum_all<<<dim3(256, 4), 256>>>();
    fz_all<<<dim3(8, 4), 256>>>(fcw, fcb);
    att_all<<<dim3(32, 4), 256>>>(fcsw, fcsb);
    wsum_all<<<5440, 256>>>(out);

    (void)n_in; (void)out_size;
}